// round 1
// baseline (speedup 1.0000x reference)
#include <cuda_runtime.h>
#include <math.h>

#define BATCH   16384
#define IN_DIM  1024
#define NE      6
#define ND      20
#define H1D     256
#define H2D     128
#define EOUT    10
#define GHID    64
#define THID    64

// ---- scratch (device globals; no allocations allowed) ----
__device__ float g_h1[BATCH * NE * H1D];     // [b][e*256+j]   ~100 MB
__device__ float g_h2[BATCH * NE * H2D];     // [b][e*128+j]   ~50 MB
__device__ float g_eo[BATCH * NE * EOUT];    // [b][e][o]      ~3.9 MB
__device__ int   g_cnt[ND];
__device__ int   g_idx[ND * BATCH];

// ------------------------------------------------------------------
// Bucketing: group samples by domain so gate/tower run only for the
// selected domain (reference computes all 20 and discards 19/20).
// Output is order-independent (each sample writes only its own rows).
// ------------------------------------------------------------------
__global__ void zero_cnt_kernel() {
    if (threadIdx.x < ND) g_cnt[threadIdx.x] = 0;
}

__global__ void bucket_kernel(const int* __restrict__ dom) {
    int b = blockIdx.x * blockDim.x + threadIdx.x;
    if (b < BATCH) {
        int d = dom[b];
        int p = atomicAdd(&g_cnt[d], 1);
        g_idx[d * BATCH + p] = b;
    }
}

// ------------------------------------------------------------------
// Generic per-expert SGEMM: C = relu(A @ W_e + bias_e)
// 128x128 tile, BK=8, 256 threads, 8x8 per-thread register tile.
//   A[row*lda + e*aKOffPerE + k]           (K window may depend on e)
//   W_e = W + e*wPerE, row-major [K][ldw], col window jb..jb+127
//   C[row*ldc + e*cpe + jb + col],  cpe = colTilesPerE*128
// ------------------------------------------------------------------
__global__ __launch_bounds__(256, 2)
void expert_gemm(const float* __restrict__ A, int lda, int aKOffPerE,
                 const float* __restrict__ W, int ldw, int wPerE,
                 const float* __restrict__ bias,
                 float* __restrict__ Cout, int ldc,
                 int colTilesPerE, int Kdim)
{
    const int e  = blockIdx.x / colTilesPerE;
    const int jb = (blockIdx.x % colTilesPerE) * 128;
    const int m0 = blockIdx.y * 128;
    const int cpe = colTilesPerE * 128;

    __shared__ float As[8][132];
    __shared__ float Bs[8][132];

    const float* Ap = A + (size_t)e * aKOffPerE;      // column (K) offset per expert
    const float* Wp = W + (size_t)e * wPerE + jb;
    const float* bp = bias + e * cpe + jb;

    const int tid  = threadIdx.x;
    const int arow = tid >> 1;            // 0..127
    const int akq  = (tid & 1) * 4;       // 0 or 4
    const int brow = tid >> 5;            // 0..7
    const int bcol = (tid & 31) * 4;      // 0..124
    const int ty   = tid >> 4;            // 0..15
    const int tx   = tid & 15;            // 0..15

    float acc[8][8];
#pragma unroll
    for (int i = 0; i < 8; i++)
#pragma unroll
        for (int j = 0; j < 8; j++) acc[i][j] = 0.f;

    for (int k0 = 0; k0 < Kdim; k0 += 8) {
        float4 av = *(const float4*)&Ap[(size_t)(m0 + arow) * lda + k0 + akq];
        As[akq + 0][arow] = av.x;
        As[akq + 1][arow] = av.y;
        As[akq + 2][arow] = av.z;
        As[akq + 3][arow] = av.w;
        float4 bv = *(const float4*)&Wp[(size_t)(k0 + brow) * ldw + bcol];
        *(float4*)&Bs[brow][bcol] = bv;
        __syncthreads();
#pragma unroll
        for (int kk = 0; kk < 8; kk++) {
            float4 a0 = *(const float4*)&As[kk][ty * 8];
            float4 a1 = *(const float4*)&As[kk][ty * 8 + 4];
            float4 b0 = *(const float4*)&Bs[kk][tx * 8];
            float4 b1 = *(const float4*)&Bs[kk][tx * 8 + 4];
            float ar[8] = {a0.x, a0.y, a0.z, a0.w, a1.x, a1.y, a1.z, a1.w};
            float br[8] = {b0.x, b0.y, b0.z, b0.w, b1.x, b1.y, b1.z, b1.w};
#pragma unroll
            for (int i = 0; i < 8; i++)
#pragma unroll
                for (int j = 0; j < 8; j++) acc[i][j] += ar[i] * br[j];
        }
        __syncthreads();
    }

#pragma unroll
    for (int i = 0; i < 8; i++) {
        int row = m0 + ty * 8 + i;
        float* crow = Cout + (size_t)row * ldc + e * cpe + jb;
#pragma unroll
        for (int j = 0; j < 8; j++) {
            int col = tx * 8 + j;
            crow[col] = fmaxf(acc[i][j] + bp[col], 0.f);
        }
    }
}

// ------------------------------------------------------------------
// Expert layer 3: eo[b][e][o] = h2[b,e,:] @ Ew3[e] + Eb3[e]
// one warp per (b,e); K=128 split over lanes; warp-reduce per output.
// ------------------------------------------------------------------
__global__ void expert_out_kernel(const float* __restrict__ W3,
                                  const float* __restrict__ b3)
{
    int gw   = (blockIdx.x * blockDim.x + threadIdx.x) >> 5;
    int lane = threadIdx.x & 31;
    if (gw >= BATCH * NE) return;
    int b = gw / NE;
    int e = gw - b * NE;

    const float* h = g_h2 + (size_t)b * (NE * H2D) + e * H2D;
    float hv[4];
#pragma unroll
    for (int q = 0; q < 4; q++) hv[q] = h[q * 32 + lane];

    const float* w = W3 + e * H2D * EOUT;
    float outv[EOUT];
#pragma unroll
    for (int o = 0; o < EOUT; o++) {
        float s = 0.f;
#pragma unroll
        for (int q = 0; q < 4; q++) s += hv[q] * w[(q * 32 + lane) * EOUT + o];
#pragma unroll
        for (int off = 16; off > 0; off >>= 1)
            s += __shfl_down_sync(0xffffffffu, s, off);
        outv[o] = s;
    }
    if (lane == 0) {
        float* dst = g_eo + (size_t)b * (NE * EOUT) + e * EOUT;
#pragma unroll
        for (int o = 0; o < EOUT; o++) dst[o] = outv[o] + b3[e * EOUT + o];
    }
}

// ------------------------------------------------------------------
// Per-domain gate GEMM (gathered rows) fused with softmax, MMoE
// combine, avg-expert output, tower MLP + sigmoid.
// grid = (ND, ceil(B/64)); block tile 64 samples x 64 hidden, K=1024.
// ------------------------------------------------------------------
__global__ __launch_bounds__(256)
void gate_tower_kernel(const float* __restrict__ X,
                       const float* __restrict__ Gw1, const float* __restrict__ Gb1,
                       const float* __restrict__ Gw2, const float* __restrict__ Gb2,
                       const float* __restrict__ Tw1, const float* __restrict__ Tb1,
                       const float* __restrict__ Tw2, const float* __restrict__ Tb2,
                       float* __restrict__ out)
{
    const int d    = blockIdx.x;
    const int base = blockIdx.y * 64;
    const int cnt  = g_cnt[d];
    if (base >= cnt) return;
    const int nrows = min(64, cnt - base);

    __shared__ float As[32][68];
    __shared__ float Bs[32][68];
    __shared__ float gh[64][68];
    __shared__ float sGw2[GHID * NE];
    __shared__ float sGb2[8];
    __shared__ float sTw1[EOUT * THID];
    __shared__ float sTb1[THID];
    __shared__ float sTw2[THID];
    __shared__ float sGb1[GHID];
    __shared__ float sTb2;
    __shared__ int   sIdx[64];

    const int tid = threadIdx.x;
    if (tid < 64)
        sIdx[tid] = (tid < nrows) ? g_idx[d * BATCH + base + tid]
                                  : g_idx[d * BATCH + base];
    for (int i = tid; i < GHID * NE; i += 256) sGw2[i] = Gw2[d * GHID * NE + i];
    if (tid < NE) sGb2[tid] = Gb2[d * NE + tid];
    for (int i = tid; i < EOUT * THID; i += 256) sTw1[i] = Tw1[d * EOUT * THID + i];
    if (tid < THID) {
        sTb1[tid] = Tb1[d * THID + tid];
        sTw2[tid] = Tw2[d * THID + tid];
        sGb1[tid] = Gb1[d * GHID + tid];
    }
    if (tid == 0) sTb2 = Tb2[d];
    __syncthreads();

    // ---- 64x64x1024 GEMM: gh = relu(X[idx] @ Gw1[d] + Gb1[d]) ----
    float acc[4][4] = {};
    const int ty = tid >> 4, tx = tid & 15;
    for (int k0 = 0; k0 < IN_DIM; k0 += 32) {
#pragma unroll
        for (int i = 0; i < 2; i++) {
            int f  = tid * 2 + i;           // 0..511
            int m  = f >> 3;                // sample row 0..63
            int kq = (f & 7) * 4;           // k 0..28
            float4 v = *(const float4*)&X[(size_t)sIdx[m] * IN_DIM + k0 + kq];
            As[kq + 0][m] = v.x; As[kq + 1][m] = v.y;
            As[kq + 2][m] = v.z; As[kq + 3][m] = v.w;
        }
#pragma unroll
        for (int i = 0; i < 2; i++) {
            int f  = tid * 2 + i;
            int kk = f >> 4;                // 0..31
            int nq = (f & 15) * 4;          // 0..60
            float4 v = *(const float4*)&Gw1[(size_t)d * IN_DIM * GHID + (size_t)(k0 + kk) * GHID + nq];
            *(float4*)&Bs[kk][nq] = v;
        }
        __syncthreads();
#pragma unroll
        for (int kk = 0; kk < 32; kk++) {
            float4 a = *(const float4*)&As[kk][ty * 4];
            float4 b = *(const float4*)&Bs[kk][tx * 4];
            float ar[4] = {a.x, a.y, a.z, a.w};
            float br[4] = {b.x, b.y, b.z, b.w};
#pragma unroll
            for (int i = 0; i < 4; i++)
#pragma unroll
                for (int j = 0; j < 4; j++) acc[i][j] += ar[i] * br[j];
        }
        __syncthreads();
    }
#pragma unroll
    for (int i = 0; i < 4; i++)
#pragma unroll
        for (int j = 0; j < 4; j++)
            gh[ty * 4 + i][tx * 4 + j] = fmaxf(acc[i][j] + sGb1[tx * 4 + j], 0.f);
    __syncthreads();

    // ---- per-sample epilogue: logits -> softmax -> mmoe -> tower ----
    if (tid < nrows) {
        const int m = tid;
        const int b = sIdx[m];

        float l[NE];
#pragma unroll
        for (int e = 0; e < NE; e++) l[e] = sGb2[e];
        for (int k = 0; k < GHID; k++) {
            float hv = gh[m][k];
#pragma unroll
            for (int e = 0; e < NE; e++) l[e] += hv * sGw2[k * NE + e];
        }
        float mx = l[0];
#pragma unroll
        for (int e = 1; e < NE; e++) mx = fmaxf(mx, l[e]);
        float ssum = 0.f;
#pragma unroll
        for (int e = 0; e < NE; e++) { l[e] = expf(l[e] - mx); ssum += l[e]; }
        float inv = 1.f / ssum;

        float mmoe[EOUT], avg[EOUT];
#pragma unroll
        for (int o = 0; o < EOUT; o++) { mmoe[o] = 0.f; avg[o] = 0.f; }
        const float* eorow = g_eo + (size_t)b * (NE * EOUT);
#pragma unroll
        for (int e = 0; e < NE; e++) {
            float gte = l[e] * inv;
#pragma unroll
            for (int o = 0; o < EOUT; o++) {
                float v = eorow[e * EOUT + o];
                mmoe[o] += gte * v;
                avg[o]  += v;
            }
        }
        // outputs: [0,B) selected_outputs | [B,11B) avg_expert_repr | [11B,21B) selected_mmoe
#pragma unroll
        for (int o = 0; o < EOUT; o++) {
            out[BATCH + (size_t)b * EOUT + o]      = avg[o] * (1.f / 6.f);
            out[11 * BATCH + (size_t)b * EOUT + o] = mmoe[o];
        }
        float tacc = sTb2;
        for (int h = 0; h < THID; h++) {
            float th = sTb1[h];
#pragma unroll
            for (int o = 0; o < EOUT; o++) th += mmoe[o] * sTw1[o * THID + h];
            th = fmaxf(th, 0.f);
            tacc += th * sTw2[h];
        }
        out[b] = 1.f / (1.f + expf(-tacc));
    }
}

// ------------------------------------------------------------------
extern "C" void kernel_launch(void* const* d_in, const int* in_sizes, int n_in,
                              void* d_out, int out_size)
{
    const float* x    = (const float*)d_in[0];
    const int*   dom  = (const int*)d_in[1];
    const float* Ew1  = (const float*)d_in[2];
    const float* Eb1  = (const float*)d_in[3];
    const float* Ew2  = (const float*)d_in[4];
    const float* Eb2  = (const float*)d_in[5];
    const float* Ew3  = (const float*)d_in[6];
    const float* Eb3  = (const float*)d_in[7];
    const float* Gw1  = (const float*)d_in[8];
    const float* Gb1  = (const float*)d_in[9];
    const float* Gw2  = (const float*)d_in[10];
    const float* Gb2  = (const float*)d_in[11];
    const float* Tw1  = (const float*)d_in[12];
    const float* Tb1  = (const float*)d_in[13];
    const float* Tw2  = (const float*)d_in[14];
    const float* Tb2  = (const float*)d_in[15];
    float* out = (float*)d_out;

    float* h1 = nullptr; float* h2 = nullptr;
    cudaGetSymbolAddress((void**)&h1, g_h1);
    cudaGetSymbolAddress((void**)&h2, g_h2);

    zero_cnt_kernel<<<1, 32>>>();
    bucket_kernel<<<(BATCH + 255) / 256, 256>>>(dom);

    // expert L1: [16384,1024] x [1024,256] per expert -> relu -> g_h1
    expert_gemm<<<dim3(NE * 2, BATCH / 128), 256>>>(
        x, IN_DIM, 0,
        Ew1, H1D, IN_DIM * H1D,
        Eb1, h1, NE * H1D,
        2, IN_DIM);

    // expert L2: [16384,256] x [256,128] per expert -> relu -> g_h2
    expert_gemm<<<dim3(NE * 1, BATCH / 128), 256>>>(
        h1, NE * H1D, H1D,
        Ew2, H2D, H1D * H2D,
        Eb2, h2, NE * H2D,
        1, H1D);

    // expert L3 -> g_eo
    {
        int warps = BATCH * NE;
        expert_out_kernel<<<(warps * 32 + 255) / 256, 256>>>(Ew3, Eb3);
    }

    // gate + softmax + mmoe + avg + tower (selected domain only)
    gate_tower_kernel<<<dim3(ND, (BATCH + 63) / 64), 256>>>(
        x, Gw1, Gb1, Gw2, Gb2, Tw1, Tb1, Tw2, Tb2, out);

    (void)in_sizes; (void)n_in; (void)out_size;
}

// round 3
// speedup vs baseline: 1.6099x; 1.6099x over previous
#include <cuda_runtime.h>
#include <cstdint>
#include <math.h>

#define BATCH   16384
#define IN_DIM  1024
#define NE      6
#define ND      20
#define H1D     256
#define H2D     128
#define EOUT    10
#define GHID    64
#define THID    64

// ---- scratch (device globals; no allocations allowed) ----
__device__ float g_h1[BATCH * NE * H1D];     // [b][e*256+j]  ~100 MB
__device__ float g_eo[BATCH * NE * EOUT];    // [b][e][o]     ~3.9 MB
__device__ int   g_cnt[ND];
__device__ int   g_idx[ND * BATCH];

// ================= helpers =================
__device__ __forceinline__ uint32_t f2tf32(float v) {
    uint32_t t; asm("cvt.rna.tf32.f32 %0, %1;" : "=r"(t) : "f"(v));
    return t;
}
__device__ __forceinline__ void mma8(float* c,
                                     uint32_t a0, uint32_t a1, uint32_t a2, uint32_t a3,
                                     uint32_t b0, uint32_t b1) {
    asm volatile(
        "mma.sync.aligned.m16n8k8.row.col.f32.tf32.tf32.f32 "
        "{%0,%1,%2,%3}, {%4,%5,%6,%7}, {%8,%9}, {%0,%1,%2,%3};"
        : "+f"(c[0]), "+f"(c[1]), "+f"(c[2]), "+f"(c[3])
        : "r"(a0), "r"(a1), "r"(a2), "r"(a3), "r"(b0), "r"(b1));
}

// SMEM float layout (per buffer): As 128x36, Bs 128x36; two buffers.
#define ASZ   (128 * 36)
#define BUFSZ (2 * ASZ)

// ================= bucketing =================
__global__ void zero_cnt_kernel() {
    if (threadIdx.x < ND) g_cnt[threadIdx.x] = 0;
}
__global__ void bucket_kernel(const int* __restrict__ dom) {
    int b = blockIdx.x * blockDim.x + threadIdx.x;
    if (b < BATCH) {
        int d = dom[b];
        int p = atomicAdd(&g_cnt[d], 1);
        g_idx[d * BATCH + p] = b;
    }
}

// ================= expert L1: tf32 mma.sync GEMM =================
// C[m][e*256 + n0 + c] = relu(X[m,:] @ Ew1[e][:, n0+c] + Eb1[e][n0+c])
// grid (128, 2, 6): x=m-block(128 rows), y=n-block(128 cols), z=expert.
__global__ __launch_bounds__(256, 1)
void expert_l1_mma(const float* __restrict__ X, const float* __restrict__ W,
                   const float* __restrict__ bias, float* __restrict__ C)
{
    extern __shared__ float sm[];
    const int tid = threadIdx.x, lane = tid & 31, wid = tid >> 5;
    const int gid = lane >> 2, tig = lane & 3;
    const int warpM = wid & 3, warpN = wid >> 2;
    const int m0 = blockIdx.x * 128;
    const int n0 = blockIdx.y * 128;
    const int e  = blockIdx.z;
    const float* Ap = X + (size_t)m0 * IN_DIM;
    const float* Bp = W + (size_t)e * IN_DIM * H1D + n0;

    float acc[2][8][4];
#pragma unroll
    for (int mt = 0; mt < 2; mt++)
#pragma unroll
        for (int nt = 0; nt < 8; nt++)
#pragma unroll
            for (int q = 0; q < 4; q++) acc[mt][nt][q] = 0.f;

    float4 aR[4], bR[4];

    auto loadg = [&](int c) {
        const int k0 = c * 32;
#pragma unroll
        for (int i = 0; i < 4; i++) {
            int f = i * 256 + tid; int m = f >> 3; int kq = (f & 7) * 4;
            aR[i] = *(const float4*)&Ap[(size_t)m * IN_DIM + k0 + kq];
        }
#pragma unroll
        for (int i = 0; i < 4; i++) {
            int f = i * 256 + tid; int k = f >> 5; int nq = (f & 31) * 4;
            bR[i] = *(const float4*)&Bp[(size_t)(k0 + k) * H1D + nq];
        }
    };
    auto stores = [&](int buf) {
        float* As_ = sm + buf * BUFSZ;
        float* Bs_ = sm + buf * BUFSZ + ASZ;
#pragma unroll
        for (int i = 0; i < 4; i++) {
            int f = i * 256 + tid; int m = f >> 3; int kd = (f & 7);
            uint32_t* p = (uint32_t*)&As_[m * 36 + kd];
            p[0]  = f2tf32(aR[i].x); p[8]  = f2tf32(aR[i].y);
            p[16] = f2tf32(aR[i].z); p[24] = f2tf32(aR[i].w);
        }
#pragma unroll
        for (int i = 0; i < 4; i++) {
            int f = i * 256 + tid; int k = f >> 5; int nq = (f & 31) * 4;
            int pk = (k & 3) * 8 + (k >> 2);
            uint32_t* p = (uint32_t*)&Bs_[nq * 36 + pk];
            p[0]   = f2tf32(bR[i].x); p[36]  = f2tf32(bR[i].y);
            p[72]  = f2tf32(bR[i].z); p[108] = f2tf32(bR[i].w);
        }
    };
    auto compute = [&](int buf) {
        const float* As_ = sm + buf * BUFSZ;
        const float* Bs_ = sm + buf * BUFSZ + ASZ;
        uint32_t Af[2][2][8];
#pragma unroll
        for (int mt = 0; mt < 2; mt++)
#pragma unroll
            for (int rr = 0; rr < 2; rr++) {
                int r = warpM * 32 + mt * 16 + gid + rr * 8;
                float4 v0 = *(const float4*)&As_[r * 36 + tig * 8];
                float4 v1 = *(const float4*)&As_[r * 36 + tig * 8 + 4];
                Af[mt][rr][0] = __float_as_uint(v0.x); Af[mt][rr][1] = __float_as_uint(v0.y);
                Af[mt][rr][2] = __float_as_uint(v0.z); Af[mt][rr][3] = __float_as_uint(v0.w);
                Af[mt][rr][4] = __float_as_uint(v1.x); Af[mt][rr][5] = __float_as_uint(v1.y);
                Af[mt][rr][6] = __float_as_uint(v1.z); Af[mt][rr][7] = __float_as_uint(v1.w);
            }
#pragma unroll
        for (int nt = 0; nt < 8; nt++) {
            int n = warpN * 64 + nt * 8 + gid;
            float4 w0 = *(const float4*)&Bs_[n * 36 + tig * 8];
            float4 w1 = *(const float4*)&Bs_[n * 36 + tig * 8 + 4];
            uint32_t Bf[8] = {
                __float_as_uint(w0.x), __float_as_uint(w0.y),
                __float_as_uint(w0.z), __float_as_uint(w0.w),
                __float_as_uint(w1.x), __float_as_uint(w1.y),
                __float_as_uint(w1.z), __float_as_uint(w1.w) };
#pragma unroll
            for (int mt = 0; mt < 2; mt++)
#pragma unroll
                for (int s = 0; s < 4; s++)
                    mma8(acc[mt][nt],
                         Af[mt][0][2*s], Af[mt][1][2*s],
                         Af[mt][0][2*s+1], Af[mt][1][2*s+1],
                         Bf[2*s], Bf[2*s+1]);
        }
    };

    constexpr int NC = IN_DIM / 32;   // 32
    loadg(0);
    stores(0);
    __syncthreads();
#pragma unroll 1
    for (int c = 0; c < NC; c++) {
        if (c + 1 < NC) loadg(c + 1);
        compute(c & 1);
        if (c + 1 < NC) {
            stores((c + 1) & 1);
            __syncthreads();
        }
    }

    // epilogue: bias + relu, direct to g_h1
#pragma unroll
    for (int mt = 0; mt < 2; mt++) {
        int rA = m0 + warpM * 32 + mt * 16 + gid;
#pragma unroll
        for (int nt = 0; nt < 8; nt++) {
            int cc = n0 + warpN * 64 + nt * 8 + tig * 2;
            float b0 = bias[e * H1D + cc];
            float b1 = bias[e * H1D + cc + 1];
            float2 v0, v1;
            v0.x = fmaxf(acc[mt][nt][0] + b0, 0.f);
            v0.y = fmaxf(acc[mt][nt][1] + b1, 0.f);
            v1.x = fmaxf(acc[mt][nt][2] + b0, 0.f);
            v1.y = fmaxf(acc[mt][nt][3] + b1, 0.f);
            *(float2*)&C[(size_t)rA * (NE * H1D) + e * H1D + cc] = v0;
            *(float2*)&C[(size_t)(rA + 8) * (NE * H1D) + e * H1D + cc] = v1;
        }
    }
}

// ================= expert L2 (+fused L3): tf32 mma.sync GEMM =================
// h2 = relu(h1[:, e*256:+256] @ Ew2[e] + Eb2[e]); eo[b][e][:] = h2 @ Ew3[e] + Eb3[e]
// grid (128, 1, 6).
__global__ __launch_bounds__(256, 1)
void expert_l2_mma(const float* __restrict__ H1, const float* __restrict__ W2,
                   const float* __restrict__ b2, const float* __restrict__ W3,
                   const float* __restrict__ b3)
{
    extern __shared__ float sm[];
    float* sW3  = sm + 2 * BUFSZ;            // 128*10
    float* sEb3 = sW3 + H2D * EOUT;          // 10

    const int tid = threadIdx.x, lane = tid & 31, wid = tid >> 5;
    const int gid = lane >> 2, tig = lane & 3;
    const int warpM = wid & 3, warpN = wid >> 2;
    const int m0 = blockIdx.x * 128;
    const int e  = blockIdx.z;
    const float* Ap = H1 + (size_t)m0 * (NE * H1D) + e * H1D;
    const float* Bp = W2 + (size_t)e * H1D * H2D;

    for (int i = tid; i < H2D * EOUT; i += 256) sW3[i] = W3[e * H2D * EOUT + i];
    if (tid < EOUT) sEb3[tid] = b3[e * EOUT + tid];

    float acc[2][8][4];
#pragma unroll
    for (int mt = 0; mt < 2; mt++)
#pragma unroll
        for (int nt = 0; nt < 8; nt++)
#pragma unroll
            for (int q = 0; q < 4; q++) acc[mt][nt][q] = 0.f;

    float4 aR[4], bR[4];

    auto loadg = [&](int c) {
        const int k0 = c * 32;
#pragma unroll
        for (int i = 0; i < 4; i++) {
            int f = i * 256 + tid; int m = f >> 3; int kq = (f & 7) * 4;
            aR[i] = *(const float4*)&Ap[(size_t)m * (NE * H1D) + k0 + kq];
        }
#pragma unroll
        for (int i = 0; i < 4; i++) {
            int f = i * 256 + tid; int k = f >> 5; int nq = (f & 31) * 4;
            bR[i] = *(const float4*)&Bp[(size_t)(k0 + k) * H2D + nq];
        }
    };
    auto stores = [&](int buf) {
        float* As_ = sm + buf * BUFSZ;
        float* Bs_ = sm + buf * BUFSZ + ASZ;
#pragma unroll
        for (int i = 0; i < 4; i++) {
            int f = i * 256 + tid; int m = f >> 3; int kd = (f & 7);
            uint32_t* p = (uint32_t*)&As_[m * 36 + kd];
            p[0]  = f2tf32(aR[i].x); p[8]  = f2tf32(aR[i].y);
            p[16] = f2tf32(aR[i].z); p[24] = f2tf32(aR[i].w);
        }
#pragma unroll
        for (int i = 0; i < 4; i++) {
            int f = i * 256 + tid; int k = f >> 5; int nq = (f & 31) * 4;
            int pk = (k & 3) * 8 + (k >> 2);
            uint32_t* p = (uint32_t*)&Bs_[nq * 36 + pk];
            p[0]   = f2tf32(bR[i].x); p[36]  = f2tf32(bR[i].y);
            p[72]  = f2tf32(bR[i].z); p[108] = f2tf32(bR[i].w);
        }
    };
    auto compute = [&](int buf) {
        const float* As_ = sm + buf * BUFSZ;
        const float* Bs_ = sm + buf * BUFSZ + ASZ;
        uint32_t Af[2][2][8];
#pragma unroll
        for (int mt = 0; mt < 2; mt++)
#pragma unroll
            for (int rr = 0; rr < 2; rr++) {
                int r = warpM * 32 + mt * 16 + gid + rr * 8;
                float4 v0 = *(const float4*)&As_[r * 36 + tig * 8];
                float4 v1 = *(const float4*)&As_[r * 36 + tig * 8 + 4];
                Af[mt][rr][0] = __float_as_uint(v0.x); Af[mt][rr][1] = __float_as_uint(v0.y);
                Af[mt][rr][2] = __float_as_uint(v0.z); Af[mt][rr][3] = __float_as_uint(v0.w);
                Af[mt][rr][4] = __float_as_uint(v1.x); Af[mt][rr][5] = __float_as_uint(v1.y);
                Af[mt][rr][6] = __float_as_uint(v1.z); Af[mt][rr][7] = __float_as_uint(v1.w);
            }
#pragma unroll
        for (int nt = 0; nt < 8; nt++) {
            int n = warpN * 64 + nt * 8 + gid;
            float4 w0 = *(const float4*)&Bs_[n * 36 + tig * 8];
            float4 w1 = *(const float4*)&Bs_[n * 36 + tig * 8 + 4];
            uint32_t Bf[8] = {
                __float_as_uint(w0.x), __float_as_uint(w0.y),
                __float_as_uint(w0.z), __float_as_uint(w0.w),
                __float_as_uint(w1.x), __float_as_uint(w1.y),
                __float_as_uint(w1.z), __float_as_uint(w1.w) };
#pragma unroll
            for (int mt = 0; mt < 2; mt++)
#pragma unroll
                for (int s = 0; s < 4; s++)
                    mma8(acc[mt][nt],
                         Af[mt][0][2*s], Af[mt][1][2*s],
                         Af[mt][0][2*s+1], Af[mt][1][2*s+1],
                         Bf[2*s], Bf[2*s+1]);
        }
    };

    constexpr int NC = H1D / 32;   // 8
    loadg(0);
    stores(0);
    __syncthreads();
#pragma unroll 1
    for (int c = 0; c < NC; c++) {
        if (c + 1 < NC) loadg(c + 1);
        compute(c & 1);
        if (c + 1 < NC) {
            stores((c + 1) & 1);
            __syncthreads();
        }
    }

    // epilogue: relu(h2 + b2) into smem (reuse buffers), then fused L3 head
    float* Cs = sm;   // [128][132]
    __syncthreads();
#pragma unroll
    for (int mt = 0; mt < 2; mt++) {
        int r = warpM * 32 + mt * 16 + gid;
#pragma unroll
        for (int nt = 0; nt < 8; nt++) {
            int cc = warpN * 64 + nt * 8 + tig * 2;
            float bb0 = b2[e * H2D + cc];
            float bb1 = b2[e * H2D + cc + 1];
            Cs[r * 132 + cc]           = fmaxf(acc[mt][nt][0] + bb0, 0.f);
            Cs[r * 132 + cc + 1]       = fmaxf(acc[mt][nt][1] + bb1, 0.f);
            Cs[(r + 8) * 132 + cc]     = fmaxf(acc[mt][nt][2] + bb0, 0.f);
            Cs[(r + 8) * 132 + cc + 1] = fmaxf(acc[mt][nt][3] + bb1, 0.f);
        }
    }
    __syncthreads();

    // L3: eo[m0+row][e][:] = Cs[row,:] @ sW3 + sEb3  (warp handles 16 rows)
    for (int rr = 0; rr < 16; rr++) {
        int row = wid * 16 + rr;
        float p[EOUT];
#pragma unroll
        for (int o = 0; o < EOUT; o++) p[o] = 0.f;
#pragma unroll
        for (int q = 0; q < 4; q++) {
            float hv = Cs[row * 132 + q * 32 + lane];
            const float* w = &sW3[(q * 32 + lane) * EOUT];
#pragma unroll
            for (int o = 0; o < EOUT; o++) p[o] += hv * w[o];
        }
#pragma unroll
        for (int off = 16; off > 0; off >>= 1)
#pragma unroll
            for (int o = 0; o < EOUT; o++)
                p[o] += __shfl_down_sync(0xffffffffu, p[o], off);
        if (lane == 0) {
            float* dst = &g_eo[(size_t)(m0 + row) * (NE * EOUT) + e * EOUT];
#pragma unroll
            for (int o = 0; o < EOUT; o++) dst[o] = p[o] + sEb3[o];
        }
    }
}

// ================= gate + softmax + mmoe + avg + tower =================
__global__ __launch_bounds__(256)
void gate_tower_kernel(const float* __restrict__ X,
                       const float* __restrict__ Gw1, const float* __restrict__ Gb1,
                       const float* __restrict__ Gw2, const float* __restrict__ Gb2,
                       const float* __restrict__ Tw1, const float* __restrict__ Tb1,
                       const float* __restrict__ Tw2, const float* __restrict__ Tb2,
                       float* __restrict__ out)
{
    const int d    = blockIdx.x;
    const int base = blockIdx.y * 64;
    const int cnt  = g_cnt[d];
    if (base >= cnt) return;
    const int nrows = min(64, cnt - base);

    __shared__ float As[32][68];
    __shared__ float Bs[32][68];
    __shared__ float gh[64][68];
    __shared__ float sGw2[GHID * NE];
    __shared__ float sGb2[8];
    __shared__ float sTw1[EOUT * THID];
    __shared__ float sTb1[THID];
    __shared__ float sTw2[THID];
    __shared__ float sGb1[GHID];
    __shared__ float sTb2;
    __shared__ int   sIdx[64];

    const int tid = threadIdx.x;
    if (tid < 64)
        sIdx[tid] = (tid < nrows) ? g_idx[d * BATCH + base + tid]
                                  : g_idx[d * BATCH + base];
    for (int i = tid; i < GHID * NE; i += 256) sGw2[i] = Gw2[d * GHID * NE + i];
    if (tid < NE) sGb2[tid] = Gb2[d * NE + tid];
    for (int i = tid; i < EOUT * THID; i += 256) sTw1[i] = Tw1[d * EOUT * THID + i];
    if (tid < THID) {
        sTb1[tid] = Tb1[d * THID + tid];
        sTw2[tid] = Tw2[d * THID + tid];
        sGb1[tid] = Gb1[d * GHID + tid];
    }
    if (tid == 0) sTb2 = Tb2[d];
    __syncthreads();

    float acc[4][4] = {};
    const int ty = tid >> 4, tx = tid & 15;
    for (int k0 = 0; k0 < IN_DIM; k0 += 32) {
#pragma unroll
        for (int i = 0; i < 2; i++) {
            int f  = tid * 2 + i;
            int m  = f >> 3;
            int kq = (f & 7) * 4;
            float4 v = *(const float4*)&X[(size_t)sIdx[m] * IN_DIM + k0 + kq];
            As[kq + 0][m] = v.x; As[kq + 1][m] = v.y;
            As[kq + 2][m] = v.z; As[kq + 3][m] = v.w;
        }
#pragma unroll
        for (int i = 0; i < 2; i++) {
            int f  = tid * 2 + i;
            int kk = f >> 4;
            int nq = (f & 15) * 4;
            float4 v = *(const float4*)&Gw1[(size_t)d * IN_DIM * GHID + (size_t)(k0 + kk) * GHID + nq];
            *(float4*)&Bs[kk][nq] = v;
        }
        __syncthreads();
#pragma unroll
        for (int kk = 0; kk < 32; kk++) {
            float4 a = *(const float4*)&As[kk][ty * 4];
            float4 b = *(const float4*)&Bs[kk][tx * 4];
            float ar[4] = {a.x, a.y, a.z, a.w};
            float br[4] = {b.x, b.y, b.z, b.w};
#pragma unroll
            for (int i = 0; i < 4; i++)
#pragma unroll
                for (int j = 0; j < 4; j++) acc[i][j] += ar[i] * br[j];
        }
        __syncthreads();
    }
#pragma unroll
    for (int i = 0; i < 4; i++)
#pragma unroll
        for (int j = 0; j < 4; j++)
            gh[ty * 4 + i][tx * 4 + j] = fmaxf(acc[i][j] + sGb1[tx * 4 + j], 0.f);
    __syncthreads();

    if (tid < nrows) {
        const int m = tid;
        const int b = sIdx[m];

        float l[NE];
#pragma unroll
        for (int e = 0; e < NE; e++) l[e] = sGb2[e];
        for (int k = 0; k < GHID; k++) {
            float hv = gh[m][k];
#pragma unroll
            for (int e = 0; e < NE; e++) l[e] += hv * sGw2[k * NE + e];
        }
        float mx = l[0];
#pragma unroll
        for (int e = 1; e < NE; e++) mx = fmaxf(mx, l[e]);
        float ssum = 0.f;
#pragma unroll
        for (int e = 0; e < NE; e++) { l[e] = expf(l[e] - mx); ssum += l[e]; }
        float inv = 1.f / ssum;

        float mmoe[EOUT], avg[EOUT];
#pragma unroll
        for (int o = 0; o < EOUT; o++) { mmoe[o] = 0.f; avg[o] = 0.f; }
        const float* eorow = g_eo + (size_t)b * (NE * EOUT);
#pragma unroll
        for (int e = 0; e < NE; e++) {
            float gte = l[e] * inv;
#pragma unroll
            for (int o = 0; o < EOUT; o++) {
                float v = eorow[e * EOUT + o];
                mmoe[o] += gte * v;
                avg[o]  += v;
            }
        }
#pragma unroll
        for (int o = 0; o < EOUT; o++) {
            out[BATCH + (size_t)b * EOUT + o]      = avg[o] * (1.f / 6.f);
            out[11 * BATCH + (size_t)b * EOUT + o] = mmoe[o];
        }
        float tacc = sTb2;
        for (int h = 0; h < THID; h++) {
            float th = sTb1[h];
#pragma unroll
            for (int o = 0; o < EOUT; o++) th += mmoe[o] * sTw1[o * THID + h];
            th = fmaxf(th, 0.f);
            tacc += th * sTw2[h];
        }
        out[b] = 1.f / (1.f + expf(-tacc));
    }
}

// ------------------------------------------------------------------
extern "C" void kernel_launch(void* const* d_in, const int* in_sizes, int n_in,
                              void* d_out, int out_size)
{
    const float* x    = (const float*)d_in[0];
    const int*   dom  = (const int*)d_in[1];
    const float* Ew1  = (const float*)d_in[2];
    const float* Eb1  = (const float*)d_in[3];
    const float* Ew2  = (const float*)d_in[4];
    const float* Eb2  = (const float*)d_in[5];
    const float* Ew3  = (const float*)d_in[6];
    const float* Eb3  = (const float*)d_in[7];
    const float* Gw1  = (const float*)d_in[8];
    const float* Gb1  = (const float*)d_in[9];
    const float* Gw2  = (const float*)d_in[10];
    const float* Gb2  = (const float*)d_in[11];
    const float* Tw1  = (const float*)d_in[12];
    const float* Tb1  = (const float*)d_in[13];
    const float* Tw2  = (const float*)d_in[14];
    const float* Tb2  = (const float*)d_in[15];
    float* out = (float*)d_out;

    float* h1 = nullptr;
    cudaGetSymbolAddress((void**)&h1, g_h1);

    const int SMEM1 = 2 * BUFSZ * 4;                               // 73728 B
    const int SMEM2 = (2 * BUFSZ + H2D * EOUT + 16) * 4;           // ~78912 B
    cudaFuncSetAttribute(expert_l1_mma, cudaFuncAttributeMaxDynamicSharedMemorySize, SMEM1);
    cudaFuncSetAttribute(expert_l2_mma, cudaFuncAttributeMaxDynamicSharedMemorySize, SMEM2);

    zero_cnt_kernel<<<1, 32>>>();
    bucket_kernel<<<(BATCH + 255) / 256, 256>>>(dom);

    expert_l1_mma<<<dim3(BATCH / 128, 2, NE), 256, SMEM1>>>(x, Ew1, Eb1, h1);
    expert_l2_mma<<<dim3(BATCH / 128, 1, NE), 256, SMEM2>>>(h1, Ew2, Eb2, Ew3, Eb3);

    gate_tower_kernel<<<dim3(ND, (BATCH + 63) / 64), 256>>>(
        x, Gw1, Gb1, Gw2, Gb2, Tw1, Tb1, Tw2, Tb2, out);

    (void)in_sizes; (void)n_in; (void)out_size;
}

// round 4
// speedup vs baseline: 2.4252x; 1.5064x over previous
#include <cuda_runtime.h>
#include <cstdint>
#include <math.h>

#define BATCH   16384
#define IN_DIM  1024
#define NE      6
#define ND      20
#define H1D     256
#define H2D     128
#define EOUT    10
#define GHID    64
#define THID    64

// ---- scratch (device globals; no allocations allowed) ----
__device__ uint32_t g_xT[BATCH * IN_DIM];       // tf32 bits, permuted per 32-chunk  (64 MB)
__device__ uint32_t g_w1T[NE * H1D * IN_DIM];   // tf32 bits, [e][n][k-permuted]     (6 MB)
__device__ uint32_t g_w2T[NE * H2D * H1D];      // tf32 bits, [e][n][k-permuted]     (0.75 MB)
__device__ uint32_t g_h1[BATCH * NE * H1D];     // tf32 bits, [m][e*256 + perm]      (100 MB)
__device__ float    g_eo[BATCH * NE * EOUT];    // fp32 [b][e][o]                    (3.9 MB)
__device__ int      g_cnt[ND];
__device__ int      g_idx[ND * BATCH];

// ================= helpers =================
__device__ __forceinline__ uint32_t f2tf32(float v) {
    uint32_t t; asm("cvt.rna.tf32.f32 %0, %1;" : "=r"(t) : "f"(v));
    return t;
}
__device__ __forceinline__ void mma8(float* c,
                                     uint32_t a0, uint32_t a1, uint32_t a2, uint32_t a3,
                                     uint32_t b0, uint32_t b1) {
    asm volatile(
        "mma.sync.aligned.m16n8k8.row.col.f32.tf32.tf32.f32 "
        "{%0,%1,%2,%3}, {%4,%5,%6,%7}, {%8,%9}, {%0,%1,%2,%3};"
        : "+f"(c[0]), "+f"(c[1]), "+f"(c[2]), "+f"(c[3])
        : "r"(a0), "r"(a1), "r"(a2), "r"(a3), "r"(b0), "r"(b1));
}
__device__ __forceinline__ void cp_async16(uint32_t saddr, const void* gptr) {
    asm volatile("cp.async.cg.shared.global [%0], [%1], 16;" :: "r"(saddr), "l"(gptr) : "memory");
}
#define CP_COMMIT() asm volatile("cp.async.commit_group;" ::: "memory")
template<int N> __device__ __forceinline__ void cp_wait() {
    asm volatile("cp.async.wait_group %0;" :: "n"(N) : "memory");
}
// permutation of k within a 32-wide chunk so fragment loads are contiguous LDS.128
__device__ __forceinline__ int kperm(int kk) { return 8 * (kk & 3) + (kk >> 2); }

// SMEM (uint32 units): As 128x36, Bs 128x36 per buffer; two buffers.
#define ASZ   (128 * 36)
#define BUFSZ (2 * ASZ)

// ================= bucketing =================
__global__ void zero_cnt_kernel() {
    if (threadIdx.x < ND) g_cnt[threadIdx.x] = 0;
}
__global__ void bucket_kernel(const int* __restrict__ dom) {
    int b = blockIdx.x * blockDim.x + threadIdx.x;
    if (b < BATCH) {
        int d = dom[b];
        int p = atomicAdd(&g_cnt[d], 1);
        g_idx[d * BATCH + p] = b;
    }
}

// ================= prep: X -> tf32 bits, permuted =================
__global__ void x_prep_kernel(const float* __restrict__ X) {
    int idx = blockIdx.x * 256 + threadIdx.x;      // 16M threads
    int m = idx >> 10, pos = idx & 1023;
    int c = pos >> 5, kk = pos & 31;
    g_xT[(size_t)m * IN_DIM + c * 32 + kperm(kk)] = f2tf32(X[(size_t)m * IN_DIM + pos]);
}

// ================= prep: W [e][K][N] -> [e][n][k-permuted] tf32 bits =================
__global__ void w_prep_kernel(const float* __restrict__ W, uint32_t* __restrict__ WT,
                              int K, int N) {
    __shared__ float tile[32][33];
    int e = blockIdx.z;
    int k0 = blockIdx.x * 32, n0 = blockIdx.y * 32;
    const float* Wp = W + (size_t)e * K * N;
    uint32_t* Tp = WT + (size_t)e * N * K;
    int tx = threadIdx.x, ty = threadIdx.y;        // 32 x 8
#pragma unroll
    for (int j = 0; j < 32; j += 8)
        tile[ty + j][tx] = Wp[(size_t)(k0 + ty + j) * N + n0 + tx];
    __syncthreads();
#pragma unroll
    for (int j = 0; j < 32; j += 8)                // row n = n0+ty+j, k = k0+tx
        Tp[(size_t)(n0 + ty + j) * K + k0 + kperm(tx)] = f2tf32(tile[tx][ty + j]);
}

// ================= core mma tile compute (shared by L1/L2) =================
struct Frag { float acc[2][8][4]; };

__device__ __forceinline__ void tile_compute(const uint32_t* As_, const uint32_t* Bs_,
                                             int warpM, int warpN, int gid, int tig,
                                             Frag& F)
{
    uint32_t Af[2][2][8];
#pragma unroll
    for (int mt = 0; mt < 2; mt++)
#pragma unroll
        for (int rr = 0; rr < 2; rr++) {
            int r = warpM * 32 + mt * 16 + gid + rr * 8;
            uint4 v0 = *(const uint4*)&As_[r * 36 + tig * 8];
            uint4 v1 = *(const uint4*)&As_[r * 36 + tig * 8 + 4];
            Af[mt][rr][0] = v0.x; Af[mt][rr][1] = v0.y;
            Af[mt][rr][2] = v0.z; Af[mt][rr][3] = v0.w;
            Af[mt][rr][4] = v1.x; Af[mt][rr][5] = v1.y;
            Af[mt][rr][6] = v1.z; Af[mt][rr][7] = v1.w;
        }
#pragma unroll
    for (int nt = 0; nt < 8; nt++) {
        int n = warpN * 64 + nt * 8 + gid;
        uint4 w0 = *(const uint4*)&Bs_[n * 36 + tig * 8];
        uint4 w1 = *(const uint4*)&Bs_[n * 36 + tig * 8 + 4];
        uint32_t Bf[8] = {w0.x, w0.y, w0.z, w0.w, w1.x, w1.y, w1.z, w1.w};
#pragma unroll
        for (int mt = 0; mt < 2; mt++)
#pragma unroll
            for (int s = 0; s < 4; s++)
                mma8(F.acc[mt][nt],
                     Af[mt][0][2*s], Af[mt][1][2*s],
                     Af[mt][0][2*s+1], Af[mt][1][2*s+1],
                     Bf[2*s], Bf[2*s+1]);
    }
}

__device__ __forceinline__ void tile_issue(uint32_t sbase, int buf, int tid,
                                           const uint32_t* Ac, int ldA,
                                           const uint32_t* Bc, int ldB)
{
    uint32_t sA = sbase + buf * (BUFSZ * 4);
    uint32_t sB = sA + ASZ * 4;
#pragma unroll
    for (int i = 0; i < 4; i++) {
        int f = i * 256 + tid, row = f >> 3, q = f & 7;
        cp_async16(sA + (row * 36 + q * 4) * 4, Ac + (size_t)row * ldA + q * 4);
    }
#pragma unroll
    for (int i = 0; i < 4; i++) {
        int f = i * 256 + tid, row = f >> 3, q = f & 7;
        cp_async16(sB + (row * 36 + q * 4) * 4, Bc + (size_t)row * ldB + q * 4);
    }
}

// ================= expert L1: tf32 mma.sync GEMM (cp.async, 2 CTA/SM) =================
// grid (128, 2, 6). h1 written as tf32 bits in permuted layout for L2.
__global__ __launch_bounds__(256, 2)
void expert_l1_mma(const float* __restrict__ bias)
{
    extern __shared__ uint32_t sm[];
    const uint32_t sbase = (uint32_t)__cvta_generic_to_shared(sm);
    const int tid = threadIdx.x, lane = tid & 31, wid = tid >> 5;
    const int gid = lane >> 2, tig = lane & 3;
    const int warpM = wid & 3, warpN = wid >> 2;
    const int m0 = blockIdx.x * 128;
    const int n0 = blockIdx.y * 128;
    const int e  = blockIdx.z;
    const uint32_t* Abase = g_xT + (size_t)m0 * IN_DIM;
    const uint32_t* Bbase = g_w1T + (size_t)(e * H1D + n0) * IN_DIM;

    Frag F;
#pragma unroll
    for (int mt = 0; mt < 2; mt++)
#pragma unroll
        for (int nt = 0; nt < 8; nt++)
#pragma unroll
            for (int q = 0; q < 4; q++) F.acc[mt][nt][q] = 0.f;

    constexpr int NC = IN_DIM / 32;   // 32
    tile_issue(sbase, 0, tid, Abase, IN_DIM, Bbase, IN_DIM);
    CP_COMMIT();
#pragma unroll 1
    for (int c = 0; c < NC; c++) {
        if (c) __syncthreads();
        if (c + 1 < NC) {
            tile_issue(sbase, (c + 1) & 1, tid,
                       Abase + (c + 1) * 32, IN_DIM,
                       Bbase + (c + 1) * 32, IN_DIM);
            CP_COMMIT();
            cp_wait<1>();
        } else {
            cp_wait<0>();
        }
        __syncthreads();
        const uint32_t* buf = sm + (c & 1) * BUFSZ;
        tile_compute(buf, buf + ASZ, warpM, warpN, gid, tig, F);
    }

    // epilogue: bias + relu -> tf32 bits, permuted layout into g_h1
#pragma unroll
    for (int mt = 0; mt < 2; mt++) {
        int rA = m0 + warpM * 32 + mt * 16 + gid;
#pragma unroll
        for (int nt = 0; nt < 8; nt++) {
            int nn = n0 + warpN * 64 + nt * 8 + tig * 2;   // 0..255 within expert
            float b0 = bias[e * H1D + nn];
            float b1 = bias[e * H1D + nn + 1];
            int cc = nn >> 5;
            int s0 = kperm(nn & 31), s1 = kperm((nn + 1) & 31);
            size_t base0 = (size_t)rA * (NE * H1D) + e * H1D + cc * 32;
            size_t base1 = (size_t)(rA + 8) * (NE * H1D) + e * H1D + cc * 32;
            g_h1[base0 + s0] = f2tf32(fmaxf(F.acc[mt][nt][0] + b0, 0.f));
            g_h1[base0 + s1] = f2tf32(fmaxf(F.acc[mt][nt][1] + b1, 0.f));
            g_h1[base1 + s0] = f2tf32(fmaxf(F.acc[mt][nt][2] + b0, 0.f));
            g_h1[base1 + s1] = f2tf32(fmaxf(F.acc[mt][nt][3] + b1, 0.f));
        }
    }
}

// ================= expert L2 (+fused L3) =================
// grid (128, 1, 6). A = g_h1 (tf32 bits, permuted), B = g_w2T.
__global__ __launch_bounds__(256, 2)
void expert_l2_mma(const float* __restrict__ b2, const float* __restrict__ W3,
                   const float* __restrict__ b3)
{
    extern __shared__ uint32_t sm[];
    const uint32_t sbase = (uint32_t)__cvta_generic_to_shared(sm);
    float* sW3  = (float*)(sm + 2 * BUFSZ);        // 128*10
    float* sEb3 = sW3 + H2D * EOUT;                // 10

    const int tid = threadIdx.x, lane = tid & 31, wid = tid >> 5;
    const int gid = lane >> 2, tig = lane & 3;
    const int warpM = wid & 3, warpN = wid >> 2;
    const int m0 = blockIdx.x * 128;
    const int e  = blockIdx.z;
    const uint32_t* Abase = g_h1 + (size_t)m0 * (NE * H1D) + e * H1D;
    const uint32_t* Bbase = g_w2T + (size_t)e * H2D * H1D;

    for (int i = tid; i < H2D * EOUT; i += 256) sW3[i] = W3[e * H2D * EOUT + i];
    if (tid < EOUT) sEb3[tid] = b3[e * EOUT + tid];

    Frag F;
#pragma unroll
    for (int mt = 0; mt < 2; mt++)
#pragma unroll
        for (int nt = 0; nt < 8; nt++)
#pragma unroll
            for (int q = 0; q < 4; q++) F.acc[mt][nt][q] = 0.f;

    constexpr int NC = H1D / 32;   // 8
    tile_issue(sbase, 0, tid, Abase, NE * H1D, Bbase, H1D);
    CP_COMMIT();
#pragma unroll 1
    for (int c = 0; c < NC; c++) {
        if (c) __syncthreads();
        if (c + 1 < NC) {
            tile_issue(sbase, (c + 1) & 1, tid,
                       Abase + (c + 1) * 32, NE * H1D,
                       Bbase + (c + 1) * 32, H1D);
            CP_COMMIT();
            cp_wait<1>();
        } else {
            cp_wait<0>();
        }
        __syncthreads();
        const uint32_t* buf = sm + (c & 1) * BUFSZ;
        tile_compute(buf, buf + ASZ, warpM, warpN, gid, tig, F);
    }

    // epilogue: relu(h2 + b2) into smem (buffers dead), then fused L3 head
    float* Cs = (float*)sm;   // [128][132]
    __syncthreads();
#pragma unroll
    for (int mt = 0; mt < 2; mt++) {
        int r = warpM * 32 + mt * 16 + gid;
#pragma unroll
        for (int nt = 0; nt < 8; nt++) {
            int cc = warpN * 64 + nt * 8 + tig * 2;
            float bb0 = b2[e * H2D + cc];
            float bb1 = b2[e * H2D + cc + 1];
            Cs[r * 132 + cc]           = fmaxf(F.acc[mt][nt][0] + bb0, 0.f);
            Cs[r * 132 + cc + 1]       = fmaxf(F.acc[mt][nt][1] + bb1, 0.f);
            Cs[(r + 8) * 132 + cc]     = fmaxf(F.acc[mt][nt][2] + bb0, 0.f);
            Cs[(r + 8) * 132 + cc + 1] = fmaxf(F.acc[mt][nt][3] + bb1, 0.f);
        }
    }
    __syncthreads();

    // L3: eo[m0+row][e][:] = Cs[row,:] @ sW3 + sEb3
    for (int rr = 0; rr < 16; rr++) {
        int row = wid * 16 + rr;
        float p[EOUT];
#pragma unroll
        for (int o = 0; o < EOUT; o++) p[o] = 0.f;
#pragma unroll
        for (int q = 0; q < 4; q++) {
            float hv = Cs[row * 132 + q * 32 + lane];
            const float* w = &sW3[(q * 32 + lane) * EOUT];
#pragma unroll
            for (int o = 0; o < EOUT; o++) p[o] += hv * w[o];
        }
#pragma unroll
        for (int off = 16; off > 0; off >>= 1)
#pragma unroll
            for (int o = 0; o < EOUT; o++)
                p[o] += __shfl_down_sync(0xffffffffu, p[o], off);
        if (lane == 0) {
            float* dst = &g_eo[(size_t)(m0 + row) * (NE * EOUT) + e * EOUT];
#pragma unroll
            for (int o = 0; o < EOUT; o++) dst[o] = p[o] + sEb3[o];
        }
    }
}

// ================= gate + softmax + mmoe + avg + tower =================
__global__ __launch_bounds__(256)
void gate_tower_kernel(const float* __restrict__ X,
                       const float* __restrict__ Gw1, const float* __restrict__ Gb1,
                       const float* __restrict__ Gw2, const float* __restrict__ Gb2,
                       const float* __restrict__ Tw1, const float* __restrict__ Tb1,
                       const float* __restrict__ Tw2, const float* __restrict__ Tb2,
                       float* __restrict__ out)
{
    const int d    = blockIdx.x;
    const int base = blockIdx.y * 64;
    const int cnt  = g_cnt[d];
    if (base >= cnt) return;
    const int nrows = min(64, cnt - base);

    __shared__ float As[32][68];
    __shared__ float Bs[32][68];
    __shared__ float gh[64][68];
    __shared__ float sGw2[GHID * NE];
    __shared__ float sGb2[8];
    __shared__ float sTw1[EOUT * THID];
    __shared__ float sTb1[THID];
    __shared__ float sTw2[THID];
    __shared__ float sGb1[GHID];
    __shared__ float sTb2;
    __shared__ int   sIdx[64];

    const int tid = threadIdx.x;
    if (tid < 64)
        sIdx[tid] = (tid < nrows) ? g_idx[d * BATCH + base + tid]
                                  : g_idx[d * BATCH + base];
    for (int i = tid; i < GHID * NE; i += 256) sGw2[i] = Gw2[d * GHID * NE + i];
    if (tid < NE) sGb2[tid] = Gb2[d * NE + tid];
    for (int i = tid; i < EOUT * THID; i += 256) sTw1[i] = Tw1[d * EOUT * THID + i];
    if (tid < THID) {
        sTb1[tid] = Tb1[d * THID + tid];
        sTw2[tid] = Tw2[d * THID + tid];
        sGb1[tid] = Gb1[d * GHID + tid];
    }
    if (tid == 0) sTb2 = Tb2[d];
    __syncthreads();

    float acc[4][4] = {};
    const int ty = tid >> 4, tx = tid & 15;
    for (int k0 = 0; k0 < IN_DIM; k0 += 32) {
#pragma unroll
        for (int i = 0; i < 2; i++) {
            int f  = tid * 2 + i;
            int m  = f >> 3;
            int kq = (f & 7) * 4;
            float4 v = *(const float4*)&X[(size_t)sIdx[m] * IN_DIM + k0 + kq];
            As[kq + 0][m] = v.x; As[kq + 1][m] = v.y;
            As[kq + 2][m] = v.z; As[kq + 3][m] = v.w;
        }
#pragma unroll
        for (int i = 0; i < 2; i++) {
            int f  = tid * 2 + i;
            int kk = f >> 4;
            int nq = (f & 15) * 4;
            float4 v = *(const float4*)&Gw1[(size_t)d * IN_DIM * GHID + (size_t)(k0 + kk) * GHID + nq];
            *(float4*)&Bs[kk][nq] = v;
        }
        __syncthreads();
#pragma unroll
        for (int kk = 0; kk < 32; kk++) {
            float4 a = *(const float4*)&As[kk][ty * 4];
            float4 b = *(const float4*)&Bs[kk][tx * 4];
            float ar[4] = {a.x, a.y, a.z, a.w};
            float br[4] = {b.x, b.y, b.z, b.w};
#pragma unroll
            for (int i = 0; i < 4; i++)
#pragma unroll
                for (int j = 0; j < 4; j++) acc[i][j] += ar[i] * br[j];
        }
        __syncthreads();
    }
#pragma unroll
    for (int i = 0; i < 4; i++)
#pragma unroll
        for (int j = 0; j < 4; j++)
            gh[ty * 4 + i][tx * 4 + j] = fmaxf(acc[i][j] + sGb1[tx * 4 + j], 0.f);
    __syncthreads();

    if (tid < nrows) {
        const int m = tid;
        const int b = sIdx[m];

        float l[NE];
#pragma unroll
        for (int e = 0; e < NE; e++) l[e] = sGb2[e];
        for (int k = 0; k < GHID; k++) {
            float hv = gh[m][k];
#pragma unroll
            for (int e = 0; e < NE; e++) l[e] += hv * sGw2[k * NE + e];
        }
        float mx = l[0];
#pragma unroll
        for (int e = 1; e < NE; e++) mx = fmaxf(mx, l[e]);
        float ssum = 0.f;
#pragma unroll
        for (int e = 0; e < NE; e++) { l[e] = expf(l[e] - mx); ssum += l[e]; }
        float inv = 1.f / ssum;

        float mmoe[EOUT], avg[EOUT];
#pragma unroll
        for (int o = 0; o < EOUT; o++) { mmoe[o] = 0.f; avg[o] = 0.f; }
        const float* eorow = g_eo + (size_t)b * (NE * EOUT);
#pragma unroll
        for (int e = 0; e < NE; e++) {
            float gte = l[e] * inv;
#pragma unroll
            for (int o = 0; o < EOUT; o++) {
                float v = eorow[e * EOUT + o];
                mmoe[o] += gte * v;
                avg[o]  += v;
            }
        }
#pragma unroll
        for (int o = 0; o < EOUT; o++) {
            out[BATCH + (size_t)b * EOUT + o]      = avg[o] * (1.f / 6.f);
            out[11 * BATCH + (size_t)b * EOUT + o] = mmoe[o];
        }
        float tacc = sTb2;
        for (int h = 0; h < THID; h++) {
            float th = sTb1[h];
#pragma unroll
            for (int o = 0; o < EOUT; o++) th += mmoe[o] * sTw1[o * THID + h];
            th = fmaxf(th, 0.f);
            tacc += th * sTw2[h];
        }
        out[b] = 1.f / (1.f + expf(-tacc));
    }
}

// ------------------------------------------------------------------
extern "C" void kernel_launch(void* const* d_in, const int* in_sizes, int n_in,
                              void* d_out, int out_size)
{
    const float* x    = (const float*)d_in[0];
    const int*   dom  = (const int*)d_in[1];
    const float* Ew1  = (const float*)d_in[2];
    const float* Eb1  = (const float*)d_in[3];
    const float* Ew2  = (const float*)d_in[4];
    const float* Eb2  = (const float*)d_in[5];
    const float* Ew3  = (const float*)d_in[6];
    const float* Eb3  = (const float*)d_in[7];
    const float* Gw1  = (const float*)d_in[8];
    const float* Gb1  = (const float*)d_in[9];
    const float* Gw2  = (const float*)d_in[10];
    const float* Gb2  = (const float*)d_in[11];
    const float* Tw1  = (const float*)d_in[12];
    const float* Tb1  = (const float*)d_in[13];
    const float* Tw2  = (const float*)d_in[14];
    const float* Tb2  = (const float*)d_in[15];
    float* out = (float*)d_out;

    uint32_t* w1T = nullptr; uint32_t* w2T = nullptr;
    cudaGetSymbolAddress((void**)&w1T, g_w1T);
    cudaGetSymbolAddress((void**)&w2T, g_w2T);

    const int SMEM1 = 2 * BUFSZ * 4;                               // 73728 B
    const int SMEM2 = 2 * BUFSZ * 4 + (H2D * EOUT + 16) * 4;       // 78912 B
    cudaFuncSetAttribute(expert_l1_mma, cudaFuncAttributeMaxDynamicSharedMemorySize, SMEM1);
    cudaFuncSetAttribute(expert_l2_mma, cudaFuncAttributeMaxDynamicSharedMemorySize, SMEM2);

    zero_cnt_kernel<<<1, 32>>>();
    bucket_kernel<<<(BATCH + 255) / 256, 256>>>(dom);

    // prep: convert/transpose/permute once
    x_prep_kernel<<<(BATCH * IN_DIM) / 256, 256>>>(x);
    w_prep_kernel<<<dim3(IN_DIM / 32, H1D / 32, NE), dim3(32, 8)>>>(Ew1, w1T, IN_DIM, H1D);
    w_prep_kernel<<<dim3(H1D / 32, H2D / 32, NE), dim3(32, 8)>>>(Ew2, w2T, H1D, H2D);

    expert_l1_mma<<<dim3(BATCH / 128, 2, NE), 256, SMEM1>>>(Eb1);
    expert_l2_mma<<<dim3(BATCH / 128, 1, NE), 256, SMEM2>>>(Eb2, Ew3, Eb3);

    gate_tower_kernel<<<dim3(ND, (BATCH + 63) / 64), 256>>>(
        x, Gw1, Gb1, Gw2, Gb2, Tw1, Tb1, Tw2, Tb2, out);

    (void)in_sizes; (void)n_in; (void)out_size;
}

// round 5
// speedup vs baseline: 3.8225x; 1.5762x over previous
#include <cuda_runtime.h>
#include <cuda_fp16.h>
#include <cstdint>
#include <math.h>

#define BATCH   16384
#define IN_DIM  1024
#define NE      6
#define ND      20
#define H1D     256
#define H2D     128
#define EOUT    10
#define GHID    64
#define THID    64

// ---- scratch (device globals; no allocations allowed) ----
__device__ __half g_xh[BATCH * IN_DIM];        // fp16, k-permuted per 32-chunk (32 MB)
__device__ __half g_w1h[NE * H1D * IN_DIM];    // fp16, [e][n][k-perm]          (3 MB)
__device__ __half g_w2h[NE * H2D * H1D];       // fp16, [e][n][k-perm]          (384 KB)
__device__ __half g_h1h[BATCH * NE * H1D];     // fp16, [m][e*256 + perm]       (50 MB)
__device__ float  g_eo[BATCH * NE * EOUT];     // fp32 [b][e][o]                (3.9 MB)
__device__ int    g_cnt[ND];
__device__ int    g_idx[ND * BATCH];

// ================= helpers =================
// k-permutation within a 32-chunk: thread-in-group t (= (k&7)>>1) gets its 8
// needed halves {2t,2t+1, +8, +16, +24} contiguous -> one LDS.128 per K=32.
__device__ __host__ __forceinline__ int perm16(int k) {
    return ((k & 7) >> 1) * 8 + (k >> 3) * 2 + (k & 1);
}
__device__ __forceinline__ void mma16(float* c,
                                      uint32_t a0, uint32_t a1, uint32_t a2, uint32_t a3,
                                      uint32_t b0, uint32_t b1) {
    asm volatile(
        "mma.sync.aligned.m16n8k16.row.col.f32.f16.f16.f32 "
        "{%0,%1,%2,%3}, {%4,%5,%6,%7}, {%8,%9}, {%0,%1,%2,%3};"
        : "+f"(c[0]), "+f"(c[1]), "+f"(c[2]), "+f"(c[3])
        : "r"(a0), "r"(a1), "r"(a2), "r"(a3), "r"(b0), "r"(b1));
}
__device__ __forceinline__ void cp_async16(uint32_t saddr, const void* gptr) {
    asm volatile("cp.async.cg.shared.global [%0], [%1], 16;" :: "r"(saddr), "l"(gptr) : "memory");
}
#define CP_COMMIT() asm volatile("cp.async.commit_group;" ::: "memory")
template<int N> __device__ __forceinline__ void cp_wait() {
    asm volatile("cp.async.wait_group %0;" :: "n"(N) : "memory");
}

// SMEM ring: stage = A(128x64B) + B(128x64B) = 16 KB; 4 stages = 64 KB.
#define STAGE_BYTES 16384
#define NSTAGE      4
#define RING_BYTES  (NSTAGE * STAGE_BYTES)

// ================= bucketing =================
__global__ void zero_cnt_kernel() {
    if (threadIdx.x < ND) g_cnt[threadIdx.x] = 0;
}
__global__ void bucket_kernel(const int* __restrict__ dom) {
    int b = blockIdx.x * blockDim.x + threadIdx.x;
    if (b < BATCH) {
        int d = dom[b];
        int p = atomicAdd(&g_cnt[d], 1);
        g_idx[d * BATCH + p] = b;
    }
}

// ================= prep: X -> fp16, k-permuted =================
__global__ void x_prep_kernel(const float* __restrict__ X) {
    int idx = blockIdx.x * 256 + threadIdx.x;
    int m = idx >> 10, pos = idx & 1023;
    int c = pos >> 5, kk = pos & 31;
    g_xh[(size_t)m * IN_DIM + c * 32 + perm16(kk)] = __float2half_rn(X[idx]);
}

// ================= prep: W [e][K][N] -> [e][n][k-perm] fp16 =================
__global__ void w_prep_kernel(const float* __restrict__ W, __half* __restrict__ WT,
                              int K, int N) {
    __shared__ float tile[32][33];
    int e = blockIdx.z;
    int k0 = blockIdx.x * 32, n0 = blockIdx.y * 32;
    const float* Wp = W + (size_t)e * K * N;
    __half* Tp = WT + (size_t)e * N * K;
    int tx = threadIdx.x, ty = threadIdx.y;   // 32 x 8
#pragma unroll
    for (int j = 0; j < 32; j += 8)
        tile[ty + j][tx] = Wp[(size_t)(k0 + ty + j) * N + n0 + tx];
    __syncthreads();
#pragma unroll
    for (int j = 0; j < 32; j += 8)
        Tp[(size_t)(n0 + ty + j) * K + k0 + perm16(tx)] = __float2half_rn(tile[tx][ty + j]);
}

// ================= core tile ops =================
struct Frag { float acc[2][8][4]; };

__device__ __forceinline__ void tile_issue(uint32_t sbase, int stage, int tid,
                                           const __half* Ac, int ldA,
                                           const __half* Bc, int ldB)
{
    uint32_t sA = sbase + stage * STAGE_BYTES;
    uint32_t sB = sA + 8192;
#pragma unroll
    for (int i = 0; i < 2; i++) {
        int f = i * 256 + tid, row = f >> 2, cdx = f & 3;
        cp_async16(sA + row * 64 + ((cdx ^ (row & 3)) << 4),
                   Ac + (size_t)row * ldA + cdx * 8);
    }
#pragma unroll
    for (int i = 0; i < 2; i++) {
        int f = i * 256 + tid, row = f >> 2, cdx = f & 3;
        cp_async16(sB + row * 64 + ((cdx ^ (row & 3)) << 4),
                   Bc + (size_t)row * ldB + cdx * 8);
    }
}

__device__ __forceinline__ void tile_compute(const char* smc, int stage,
                                             int warpM, int warpN, int gid, int tig,
                                             Frag& F)
{
    const char* st = smc + stage * STAGE_BYTES;
    uint4 Ar[2][2];
#pragma unroll
    for (int mt = 0; mt < 2; mt++)
#pragma unroll
        for (int rr = 0; rr < 2; rr++) {
            int r = warpM * 32 + mt * 16 + rr * 8 + gid;
            Ar[mt][rr] = *(const uint4*)(st + r * 64 + ((tig ^ (r & 3)) << 4));
        }
#pragma unroll
    for (int nt = 0; nt < 8; nt++) {
        int n = warpN * 64 + nt * 8 + gid;
        uint4 Br = *(const uint4*)(st + 8192 + n * 64 + ((tig ^ (n & 3)) << 4));
#pragma unroll
        for (int mt = 0; mt < 2; mt++) {
            mma16(F.acc[mt][nt], Ar[mt][0].x, Ar[mt][1].x, Ar[mt][0].y, Ar[mt][1].y, Br.x, Br.y);
            mma16(F.acc[mt][nt], Ar[mt][0].z, Ar[mt][1].z, Ar[mt][0].w, Ar[mt][1].w, Br.z, Br.w);
        }
    }
}

// ================= expert L1: fp16 mma GEMM =================
// grid (128, 2, 6): m-block, n-block(128 of 256), expert. Output: fp16 permuted h1.
__global__ __launch_bounds__(256, 2)
void expert_l1_mma(const float* __restrict__ bias)
{
    extern __shared__ uint32_t sm[];
    const uint32_t sbase = (uint32_t)__cvta_generic_to_shared(sm);
    const char* smc = (const char*)sm;
    const int tid = threadIdx.x, lane = tid & 31, wid = tid >> 5;
    const int gid = lane >> 2, tig = lane & 3;
    const int warpM = wid & 3, warpN = wid >> 2;
    const int m0 = blockIdx.x * 128;
    const int n0 = blockIdx.y * 128;
    const int e  = blockIdx.z;
    const __half* Abase = g_xh + (size_t)m0 * IN_DIM;
    const __half* Bbase = g_w1h + (size_t)(e * H1D + n0) * IN_DIM;

    Frag F;
#pragma unroll
    for (int mt = 0; mt < 2; mt++)
#pragma unroll
        for (int nt = 0; nt < 8; nt++)
#pragma unroll
            for (int q = 0; q < 4; q++) F.acc[mt][nt][q] = 0.f;

    constexpr int NC = IN_DIM / 32;   // 32
#pragma unroll
    for (int s = 0; s < NSTAGE - 1; s++) {
        tile_issue(sbase, s, tid, Abase + s * 32, IN_DIM, Bbase + s * 32, IN_DIM);
        CP_COMMIT();
    }
#pragma unroll 1
    for (int c = 0; c < NC; c++) {
        cp_wait<NSTAGE - 2>();
        __syncthreads();
        int nxt = c + NSTAGE - 1;
        if (nxt < NC)
            tile_issue(sbase, nxt & (NSTAGE - 1), tid,
                       Abase + nxt * 32, IN_DIM, Bbase + nxt * 32, IN_DIM);
        CP_COMMIT();
        tile_compute(smc, c & (NSTAGE - 1), warpM, warpN, gid, tig, F);
    }

    // epilogue: bias + relu -> fp16, permuted layout into g_h1h
#pragma unroll
    for (int mt = 0; mt < 2; mt++) {
        int rA = m0 + warpM * 32 + mt * 16 + gid;
#pragma unroll
        for (int nt = 0; nt < 8; nt++) {
            int nn = n0 + warpN * 64 + nt * 8 + tig * 2;   // even, 0..255
            float b0 = bias[e * H1D + nn];
            float b1 = bias[e * H1D + nn + 1];
            int w32 = nn & 31;
            int p = ((w32 & 7) >> 1) * 8 + (w32 >> 3) * 2;  // even
            size_t h0 = ((size_t)rA * (NE * H1D) + e * H1D + (nn >> 5) * 32 + p) >> 1;
            size_t h1i = ((size_t)(rA + 8) * (NE * H1D) + e * H1D + (nn >> 5) * 32 + p) >> 1;
            ((__half2*)g_h1h)[h0] = __floats2half2_rn(
                fmaxf(F.acc[mt][nt][0] + b0, 0.f), fmaxf(F.acc[mt][nt][1] + b1, 0.f));
            ((__half2*)g_h1h)[h1i] = __floats2half2_rn(
                fmaxf(F.acc[mt][nt][2] + b0, 0.f), fmaxf(F.acc[mt][nt][3] + b1, 0.f));
        }
    }
}

// ================= expert L2 (+fused L3): fp16 mma GEMM =================
// grid (128, 1, 6). A = g_h1h (fp16 permuted), B = g_w2h.
#define CS_PITCH 132
__global__ __launch_bounds__(256, 2)
void expert_l2_mma(const float* __restrict__ b2, const float* __restrict__ W3,
                   const float* __restrict__ b3)
{
    extern __shared__ uint32_t sm[];
    const uint32_t sbase = (uint32_t)__cvta_generic_to_shared(sm);
    const char* smc = (const char*)sm;
    float* sW3  = (float*)((char*)sm + 128 * CS_PITCH * 4);   // after Cs region
    float* sEb3 = sW3 + H2D * EOUT;

    const int tid = threadIdx.x, lane = tid & 31, wid = tid >> 5;
    const int gid = lane >> 2, tig = lane & 3;
    const int warpM = wid & 3, warpN = wid >> 2;
    const int m0 = blockIdx.x * 128;
    const int e  = blockIdx.z;
    const __half* Abase = g_h1h + (size_t)m0 * (NE * H1D) + e * H1D;
    const __half* Bbase = g_w2h + (size_t)e * H2D * H1D;

    for (int i = tid; i < H2D * EOUT; i += 256) sW3[i] = W3[e * H2D * EOUT + i];
    if (tid < EOUT) sEb3[tid] = b3[e * EOUT + tid];

    Frag F;
#pragma unroll
    for (int mt = 0; mt < 2; mt++)
#pragma unroll
        for (int nt = 0; nt < 8; nt++)
#pragma unroll
            for (int q = 0; q < 4; q++) F.acc[mt][nt][q] = 0.f;

    constexpr int NC = H1D / 32;   // 8
#pragma unroll
    for (int s = 0; s < NSTAGE - 1; s++) {
        tile_issue(sbase, s, tid, Abase + s * 32, NE * H1D, Bbase + s * 32, H1D);
        CP_COMMIT();
    }
#pragma unroll 1
    for (int c = 0; c < NC; c++) {
        cp_wait<NSTAGE - 2>();
        __syncthreads();
        int nxt = c + NSTAGE - 1;
        if (nxt < NC)
            tile_issue(sbase, nxt & (NSTAGE - 1), tid,
                       Abase + nxt * 32, NE * H1D, Bbase + nxt * 32, H1D);
        CP_COMMIT();
        tile_compute(smc, c & (NSTAGE - 1), warpM, warpN, gid, tig, F);
    }

    // epilogue: relu(h2 + b2) into smem (ring dead), then fused L3 head
    float* Cs = (float*)sm;
    __syncthreads();
#pragma unroll
    for (int mt = 0; mt < 2; mt++) {
        int r = warpM * 32 + mt * 16 + gid;
#pragma unroll
        for (int nt = 0; nt < 8; nt++) {
            int cc = warpN * 64 + nt * 8 + tig * 2;
            float bb0 = b2[e * H2D + cc];
            float bb1 = b2[e * H2D + cc + 1];
            Cs[r * CS_PITCH + cc]           = fmaxf(F.acc[mt][nt][0] + bb0, 0.f);
            Cs[r * CS_PITCH + cc + 1]       = fmaxf(F.acc[mt][nt][1] + bb1, 0.f);
            Cs[(r + 8) * CS_PITCH + cc]     = fmaxf(F.acc[mt][nt][2] + bb0, 0.f);
            Cs[(r + 8) * CS_PITCH + cc + 1] = fmaxf(F.acc[mt][nt][3] + bb1, 0.f);
        }
    }
    __syncthreads();

    // L3: eo[m0+row][e][:] = Cs[row,:] @ sW3 + sEb3
    for (int rr = 0; rr < 16; rr++) {
        int row = wid * 16 + rr;
        float p[EOUT];
#pragma unroll
        for (int o = 0; o < EOUT; o++) p[o] = 0.f;
#pragma unroll
        for (int q = 0; q < 4; q++) {
            float hv = Cs[row * CS_PITCH + q * 32 + lane];
            const float* w = &sW3[(q * 32 + lane) * EOUT];
#pragma unroll
            for (int o = 0; o < EOUT; o++) p[o] += hv * w[o];
        }
#pragma unroll
        for (int off = 16; off > 0; off >>= 1)
#pragma unroll
            for (int o = 0; o < EOUT; o++)
                p[o] += __shfl_down_sync(0xffffffffu, p[o], off);
        if (lane == 0) {
            float* dst = &g_eo[(size_t)(m0 + row) * (NE * EOUT) + e * EOUT];
#pragma unroll
            for (int o = 0; o < EOUT; o++) dst[o] = p[o] + sEb3[o];
        }
    }
}

// ================= gate + softmax + mmoe + avg + tower =================
__global__ __launch_bounds__(256)
void gate_tower_kernel(const float* __restrict__ X,
                       const float* __restrict__ Gw1, const float* __restrict__ Gb1,
                       const float* __restrict__ Gw2, const float* __restrict__ Gb2,
                       const float* __restrict__ Tw1, const float* __restrict__ Tb1,
                       const float* __restrict__ Tw2, const float* __restrict__ Tb2,
                       float* __restrict__ out)
{
    const int d    = blockIdx.x;
    const int base = blockIdx.y * 64;
    const int cnt  = g_cnt[d];
    if (base >= cnt) return;
    const int nrows = min(64, cnt - base);

    __shared__ float As[32][68];
    __shared__ float Bs[32][68];
    __shared__ float gh[64][68];
    __shared__ float sGw2[GHID * NE];
    __shared__ float sGb2[8];
    __shared__ float sTw1[EOUT * THID];
    __shared__ float sTb1[THID];
    __shared__ float sTw2[THID];
    __shared__ float sGb1[GHID];
    __shared__ float sTb2;
    __shared__ int   sIdx[64];

    const int tid = threadIdx.x;
    if (tid < 64)
        sIdx[tid] = (tid < nrows) ? g_idx[d * BATCH + base + tid]
                                  : g_idx[d * BATCH + base];
    for (int i = tid; i < GHID * NE; i += 256) sGw2[i] = Gw2[d * GHID * NE + i];
    if (tid < NE) sGb2[tid] = Gb2[d * NE + tid];
    for (int i = tid; i < EOUT * THID; i += 256) sTw1[i] = Tw1[d * EOUT * THID + i];
    if (tid < THID) {
        sTb1[tid] = Tb1[d * THID + tid];
        sTw2[tid] = Tw2[d * THID + tid];
        sGb1[tid] = Gb1[d * GHID + tid];
    }
    if (tid == 0) sTb2 = Tb2[d];
    __syncthreads();

    float acc[4][4] = {};
    const int ty = tid >> 4, tx = tid & 15;
    for (int k0 = 0; k0 < IN_DIM; k0 += 32) {
#pragma unroll
        for (int i = 0; i < 2; i++) {
            int f  = tid * 2 + i;
            int m  = f >> 3;
            int kq = (f & 7) * 4;
            float4 v = *(const float4*)&X[(size_t)sIdx[m] * IN_DIM + k0 + kq];
            As[kq + 0][m] = v.x; As[kq + 1][m] = v.y;
            As[kq + 2][m] = v.z; As[kq + 3][m] = v.w;
        }
#pragma unroll
        for (int i = 0; i < 2; i++) {
            int f  = tid * 2 + i;
            int kk = f >> 4;
            int nq = (f & 15) * 4;
            float4 v = *(const float4*)&Gw1[(size_t)d * IN_DIM * GHID + (size_t)(k0 + kk) * GHID + nq];
            *(float4*)&Bs[kk][nq] = v;
        }
        __syncthreads();
#pragma unroll
        for (int kk = 0; kk < 32; kk++) {
            float4 a = *(const float4*)&As[kk][ty * 4];
            float4 b = *(const float4*)&Bs[kk][tx * 4];
            float ar[4] = {a.x, a.y, a.z, a.w};
            float br[4] = {b.x, b.y, b.z, b.w};
#pragma unroll
            for (int i = 0; i < 4; i++)
#pragma unroll
                for (int j = 0; j < 4; j++) acc[i][j] += ar[i] * br[j];
        }
        __syncthreads();
    }
#pragma unroll
    for (int i = 0; i < 4; i++)
#pragma unroll
        for (int j = 0; j < 4; j++)
            gh[ty * 4 + i][tx * 4 + j] = fmaxf(acc[i][j] + sGb1[tx * 4 + j], 0.f);
    __syncthreads();

    if (tid < nrows) {
        const int m = tid;
        const int b = sIdx[m];

        float l[NE];
#pragma unroll
        for (int e = 0; e < NE; e++) l[e] = sGb2[e];
        for (int k = 0; k < GHID; k++) {
            float hv = gh[m][k];
#pragma unroll
            for (int e = 0; e < NE; e++) l[e] += hv * sGw2[k * NE + e];
        }
        float mx = l[0];
#pragma unroll
        for (int e = 1; e < NE; e++) mx = fmaxf(mx, l[e]);
        float ssum = 0.f;
#pragma unroll
        for (int e = 0; e < NE; e++) { l[e] = expf(l[e] - mx); ssum += l[e]; }
        float inv = 1.f / ssum;

        float mmoe[EOUT], avg[EOUT];
#pragma unroll
        for (int o = 0; o < EOUT; o++) { mmoe[o] = 0.f; avg[o] = 0.f; }
        const float* eorow = g_eo + (size_t)b * (NE * EOUT);
#pragma unroll
        for (int e = 0; e < NE; e++) {
            float gte = l[e] * inv;
#pragma unroll
            for (int o = 0; o < EOUT; o++) {
                float v = eorow[e * EOUT + o];
                mmoe[o] += gte * v;
                avg[o]  += v;
            }
        }
#pragma unroll
        for (int o = 0; o < EOUT; o++) {
            out[BATCH + (size_t)b * EOUT + o]      = avg[o] * (1.f / 6.f);
            out[11 * BATCH + (size_t)b * EOUT + o] = mmoe[o];
        }
        float tacc = sTb2;
        for (int h = 0; h < THID; h++) {
            float th = sTb1[h];
#pragma unroll
            for (int o = 0; o < EOUT; o++) th += mmoe[o] * sTw1[o * THID + h];
            th = fmaxf(th, 0.f);
            tacc += th * sTw2[h];
        }
        out[b] = 1.f / (1.f + expf(-tacc));
    }
}

// ------------------------------------------------------------------
extern "C" void kernel_launch(void* const* d_in, const int* in_sizes, int n_in,
                              void* d_out, int out_size)
{
    const float* x    = (const float*)d_in[0];
    const int*   dom  = (const int*)d_in[1];
    const float* Ew1  = (const float*)d_in[2];
    const float* Eb1  = (const float*)d_in[3];
    const float* Ew2  = (const float*)d_in[4];
    const float* Eb2  = (const float*)d_in[5];
    const float* Ew3  = (const float*)d_in[6];
    const float* Eb3  = (const float*)d_in[7];
    const float* Gw1  = (const float*)d_in[8];
    const float* Gb1  = (const float*)d_in[9];
    const float* Gw2  = (const float*)d_in[10];
    const float* Gb2  = (const float*)d_in[11];
    const float* Tw1  = (const float*)d_in[12];
    const float* Tb1  = (const float*)d_in[13];
    const float* Tw2  = (const float*)d_in[14];
    const float* Tb2  = (const float*)d_in[15];
    float* out = (float*)d_out;

    __half* w1h = nullptr; __half* w2h = nullptr;
    cudaGetSymbolAddress((void**)&w1h, g_w1h);
    cudaGetSymbolAddress((void**)&w2h, g_w2h);

    const int SMEM1 = RING_BYTES;                                   // 65536
    const int SMEM2 = 128 * CS_PITCH * 4 + (H2D * EOUT + 16) * 4;   // 72768
    cudaFuncSetAttribute(expert_l1_mma, cudaFuncAttributeMaxDynamicSharedMemorySize, SMEM1);
    cudaFuncSetAttribute(expert_l2_mma, cudaFuncAttributeMaxDynamicSharedMemorySize, SMEM2);

    zero_cnt_kernel<<<1, 32>>>();
    bucket_kernel<<<(BATCH + 255) / 256, 256>>>(dom);

    x_prep_kernel<<<(BATCH * IN_DIM) / 256, 256>>>(x);
    w_prep_kernel<<<dim3(IN_DIM / 32, H1D / 32, NE), dim3(32, 8)>>>(Ew1, w1h, IN_DIM, H1D);
    w_prep_kernel<<<dim3(H1D / 32, H2D / 32, NE), dim3(32, 8)>>>(Ew2, w2h, H1D, H2D);

    expert_l1_mma<<<dim3(BATCH / 128, 2, NE), 256, SMEM1>>>(Eb1);
    expert_l2_mma<<<dim3(BATCH / 128, 1, NE), 256, SMEM2>>>(Eb2, Ew3, Eb3);

    gate_tower_kernel<<<dim3(ND, (BATCH + 63) / 64), 256>>>(
        x, Gw1, Gb1, Gw2, Gb2, Tw1, Tb1, Tw2, Tb2, out);

    (void)in_sizes; (void)n_in; (void)out_size;
}

// round 7
// speedup vs baseline: 5.5139x; 1.4425x over previous
#include <cuda_runtime.h>
#include <cuda_fp16.h>
#include <cstdint>
#include <math.h>

#define BATCH   16384
#define IN_DIM  1024
#define NE      6
#define ND      20
#define H1D     256
#define H2D     128
#define EOUT    10
#define GHID    64
#define THID    64

// ---- scratch (device globals; no allocations allowed) ----
__device__ __half g_xh[BATCH * IN_DIM];        // fp16, k-permuted per 32-chunk (32 MB)
__device__ __half g_w1h[NE * H1D * IN_DIM];    // fp16, [e][n][k-perm]          (3 MB)
__device__ __half g_w2h[NE * H2D * H1D];       // fp16, [e][n][k-perm]          (384 KB)
__device__ __half g_gw1h[ND * GHID * IN_DIM];  // fp16, [d][n][k-perm]          (2.6 MB)
__device__ __half g_h1h[BATCH * NE * H1D];     // fp16, [m][e*256 + perm]       (50 MB)
__device__ float  g_eo[BATCH * NE * EOUT];     // fp32 [b][e][o]                (3.9 MB)
__device__ int    g_cnt[ND];
__device__ int    g_idx[ND * BATCH];

// ================= helpers =================
__device__ __forceinline__ uint32_t h2_as_u32(__half2 h) {
    return *(uint32_t*)&h;
}
// k-permutation within a 32-chunk: thread-in-group t (= (k&7)>>1) gets its 8
// needed halves {2t,2t+1, +8, +16, +24} contiguous -> one LDS.128 per K=32.
__device__ __host__ __forceinline__ int perm16(int k) {
    return ((k & 7) >> 1) * 8 + (k >> 3) * 2 + (k & 1);
}
__device__ __forceinline__ void mma16(float* c,
                                      uint32_t a0, uint32_t a1, uint32_t a2, uint32_t a3,
                                      uint32_t b0, uint32_t b1) {
    asm volatile(
        "mma.sync.aligned.m16n8k16.row.col.f32.f16.f16.f32 "
        "{%0,%1,%2,%3}, {%4,%5,%6,%7}, {%8,%9}, {%0,%1,%2,%3};"
        : "+f"(c[0]), "+f"(c[1]), "+f"(c[2]), "+f"(c[3])
        : "r"(a0), "r"(a1), "r"(a2), "r"(a3), "r"(b0), "r"(b1));
}
__device__ __forceinline__ void cp_async16(uint32_t saddr, const void* gptr) {
    asm volatile("cp.async.cg.shared.global [%0], [%1], 16;" :: "r"(saddr), "l"(gptr) : "memory");
}
#define CP_COMMIT() asm volatile("cp.async.commit_group;" ::: "memory")
template<int N> __device__ __forceinline__ void cp_wait() {
    asm volatile("cp.async.wait_group %0;" :: "n"(N) : "memory");
}

// Expert SMEM ring: stage = A(128x64B) + B(128x64B) = 16 KB; 4 stages.
#define STAGE_BYTES 16384
#define NSTAGE      4
#define RING_BYTES  (NSTAGE * STAGE_BYTES)
// Gate SMEM ring: stage = A(64x64B) + B(64x64B) = 8 KB; 4 stages = 32 KB.
#define GSTAGE_BYTES 8192
#define GRING_BYTES  (NSTAGE * GSTAGE_BYTES)

// ================= bucketing =================
__global__ void zero_cnt_kernel() {
    if (threadIdx.x < ND) g_cnt[threadIdx.x] = 0;
}
__global__ void bucket_kernel(const int* __restrict__ dom) {
    int b = blockIdx.x * blockDim.x + threadIdx.x;
    if (b < BATCH) {
        int d = dom[b];
        int p = atomicAdd(&g_cnt[d], 1);
        g_idx[d * BATCH + p] = b;
    }
}

// ================= prep: X -> fp16, k-permuted (8 elems/thread) =================
__global__ void x_prep_kernel(const float* __restrict__ X) {
    int idx = blockIdx.x * 256 + threadIdx.x;        // 2M threads
    int m = idx >> 7;
    int rest = idx & 127;
    int c = rest >> 2, t = rest & 3;                 // chunk, group
    const float* src = X + (size_t)m * IN_DIM + c * 32 + 2 * t;
    float2 v0 = *(const float2*)(src + 0);
    float2 v1 = *(const float2*)(src + 8);
    float2 v2 = *(const float2*)(src + 16);
    float2 v3 = *(const float2*)(src + 24);
    uint4 o;
    o.x = h2_as_u32(__floats2half2_rn(v0.x, v0.y));
    o.y = h2_as_u32(__floats2half2_rn(v1.x, v1.y));
    o.z = h2_as_u32(__floats2half2_rn(v2.x, v2.y));
    o.w = h2_as_u32(__floats2half2_rn(v3.x, v3.y));
    *(uint4*)(g_xh + (size_t)m * IN_DIM + c * 32 + t * 8) = o;
}

// ================= prep: W [e][K][N] -> [e][n][k-perm] fp16 =================
__global__ void w_prep_kernel(const float* __restrict__ W, __half* __restrict__ WT,
                              int K, int N) {
    __shared__ float tile[32][33];
    int e = blockIdx.z;
    int k0 = blockIdx.x * 32, n0 = blockIdx.y * 32;
    const float* Wp = W + (size_t)e * K * N;
    __half* Tp = WT + (size_t)e * N * K;
    int tx = threadIdx.x, ty = threadIdx.y;   // 32 x 8
#pragma unroll
    for (int j = 0; j < 32; j += 8)
        tile[ty + j][tx] = Wp[(size_t)(k0 + ty + j) * N + n0 + tx];
    __syncthreads();
#pragma unroll
    for (int j = 0; j < 32; j += 8)
        Tp[(size_t)(n0 + ty + j) * K + k0 + perm16(tx)] = __float2half_rn(tile[tx][ty + j]);
}

// ================= core tile ops (expert 128x128) =================
struct Frag { float acc[2][8][4]; };

__device__ __forceinline__ void tile_issue(uint32_t sbase, int stage, int tid,
                                           const __half* Ac, int ldA,
                                           const __half* Bc, int ldB)
{
    uint32_t sA = sbase + stage * STAGE_BYTES;
    uint32_t sB = sA + 8192;
#pragma unroll
    for (int i = 0; i < 2; i++) {
        int f = i * 256 + tid, row = f >> 2, cdx = f & 3;
        cp_async16(sA + row * 64 + ((cdx ^ (row & 3)) << 4),
                   Ac + (size_t)row * ldA + cdx * 8);
    }
#pragma unroll
    for (int i = 0; i < 2; i++) {
        int f = i * 256 + tid, row = f >> 2, cdx = f & 3;
        cp_async16(sB + row * 64 + ((cdx ^ (row & 3)) << 4),
                   Bc + (size_t)row * ldB + cdx * 8);
    }
}

__device__ __forceinline__ void tile_compute(const char* smc, int stage,
                                             int warpM, int warpN, int gid, int tig,
                                             Frag& F)
{
    const char* st = smc + stage * STAGE_BYTES;
    uint4 Ar[2][2];
#pragma unroll
    for (int mt = 0; mt < 2; mt++)
#pragma unroll
        for (int rr = 0; rr < 2; rr++) {
            int r = warpM * 32 + mt * 16 + rr * 8 + gid;
            Ar[mt][rr] = *(const uint4*)(st + r * 64 + ((tig ^ (r & 3)) << 4));
        }
#pragma unroll
    for (int nt = 0; nt < 8; nt++) {
        int n = warpN * 64 + nt * 8 + gid;
        uint4 Br = *(const uint4*)(st + 8192 + n * 64 + ((tig ^ (n & 3)) << 4));
#pragma unroll
        for (int mt = 0; mt < 2; mt++) {
            mma16(F.acc[mt][nt], Ar[mt][0].x, Ar[mt][1].x, Ar[mt][0].y, Ar[mt][1].y, Br.x, Br.y);
            mma16(F.acc[mt][nt], Ar[mt][0].z, Ar[mt][1].z, Ar[mt][0].w, Ar[mt][1].w, Br.z, Br.w);
        }
    }
}

// ================= expert L1: fp16 mma GEMM =================
__global__ __launch_bounds__(256, 2)
void expert_l1_mma(const float* __restrict__ bias)
{
    extern __shared__ uint32_t sm[];
    const uint32_t sbase = (uint32_t)__cvta_generic_to_shared(sm);
    const char* smc = (const char*)sm;
    const int tid = threadIdx.x, lane = tid & 31, wid = tid >> 5;
    const int gid = lane >> 2, tig = lane & 3;
    const int warpM = wid & 3, warpN = wid >> 2;
    const int m0 = blockIdx.x * 128;
    const int n0 = blockIdx.y * 128;
    const int e  = blockIdx.z;
    const __half* Abase = g_xh + (size_t)m0 * IN_DIM;
    const __half* Bbase = g_w1h + (size_t)(e * H1D + n0) * IN_DIM;

    Frag F;
#pragma unroll
    for (int mt = 0; mt < 2; mt++)
#pragma unroll
        for (int nt = 0; nt < 8; nt++)
#pragma unroll
            for (int q = 0; q < 4; q++) F.acc[mt][nt][q] = 0.f;

    constexpr int NC = IN_DIM / 32;   // 32
#pragma unroll
    for (int s = 0; s < NSTAGE - 1; s++) {
        tile_issue(sbase, s, tid, Abase + s * 32, IN_DIM, Bbase + s * 32, IN_DIM);
        CP_COMMIT();
    }
#pragma unroll 1
    for (int c = 0; c < NC; c++) {
        cp_wait<NSTAGE - 2>();
        __syncthreads();
        int nxt = c + NSTAGE - 1;
        if (nxt < NC)
            tile_issue(sbase, nxt & (NSTAGE - 1), tid,
                       Abase + nxt * 32, IN_DIM, Bbase + nxt * 32, IN_DIM);
        CP_COMMIT();
        tile_compute(smc, c & (NSTAGE - 1), warpM, warpN, gid, tig, F);
    }

    // epilogue: bias + relu -> fp16, permuted layout into g_h1h
#pragma unroll
    for (int mt = 0; mt < 2; mt++) {
        int rA = m0 + warpM * 32 + mt * 16 + gid;
#pragma unroll
        for (int nt = 0; nt < 8; nt++) {
            int nn = n0 + warpN * 64 + nt * 8 + tig * 2;   // even, 0..255
            float b0 = bias[e * H1D + nn];
            float b1 = bias[e * H1D + nn + 1];
            int w32 = nn & 31;
            int p = ((w32 & 7) >> 1) * 8 + (w32 >> 3) * 2;  // even
            size_t h0 = ((size_t)rA * (NE * H1D) + e * H1D + (nn >> 5) * 32 + p) >> 1;
            size_t h1i = ((size_t)(rA + 8) * (NE * H1D) + e * H1D + (nn >> 5) * 32 + p) >> 1;
            ((__half2*)g_h1h)[h0] = __floats2half2_rn(
                fmaxf(F.acc[mt][nt][0] + b0, 0.f), fmaxf(F.acc[mt][nt][1] + b1, 0.f));
            ((__half2*)g_h1h)[h1i] = __floats2half2_rn(
                fmaxf(F.acc[mt][nt][2] + b0, 0.f), fmaxf(F.acc[mt][nt][3] + b1, 0.f));
        }
    }
}

// ================= expert L2 (+fused L3): fp16 mma GEMM =================
#define CS_PITCH 132
__global__ __launch_bounds__(256, 2)
void expert_l2_mma(const float* __restrict__ b2, const float* __restrict__ W3,
                   const float* __restrict__ b3)
{
    extern __shared__ uint32_t sm[];
    const uint32_t sbase = (uint32_t)__cvta_generic_to_shared(sm);
    const char* smc = (const char*)sm;
    float* sW3  = (float*)((char*)sm + 128 * CS_PITCH * 4);
    float* sEb3 = sW3 + H2D * EOUT;

    const int tid = threadIdx.x, lane = tid & 31, wid = tid >> 5;
    const int gid = lane >> 2, tig = lane & 3;
    const int warpM = wid & 3, warpN = wid >> 2;
    const int m0 = blockIdx.x * 128;
    const int e  = blockIdx.z;
    const __half* Abase = g_h1h + (size_t)m0 * (NE * H1D) + e * H1D;
    const __half* Bbase = g_w2h + (size_t)e * H2D * H1D;

    for (int i = tid; i < H2D * EOUT; i += 256) sW3[i] = W3[e * H2D * EOUT + i];
    if (tid < EOUT) sEb3[tid] = b3[e * EOUT + tid];

    Frag F;
#pragma unroll
    for (int mt = 0; mt < 2; mt++)
#pragma unroll
        for (int nt = 0; nt < 8; nt++)
#pragma unroll
            for (int q = 0; q < 4; q++) F.acc[mt][nt][q] = 0.f;

    constexpr int NC = H1D / 32;   // 8
#pragma unroll
    for (int s = 0; s < NSTAGE - 1; s++) {
        tile_issue(sbase, s, tid, Abase + s * 32, NE * H1D, Bbase + s * 32, H1D);
        CP_COMMIT();
    }
#pragma unroll 1
    for (int c = 0; c < NC; c++) {
        cp_wait<NSTAGE - 2>();
        __syncthreads();
        int nxt = c + NSTAGE - 1;
        if (nxt < NC)
            tile_issue(sbase, nxt & (NSTAGE - 1), tid,
                       Abase + nxt * 32, NE * H1D, Bbase + nxt * 32, H1D);
        CP_COMMIT();
        tile_compute(smc, c & (NSTAGE - 1), warpM, warpN, gid, tig, F);
    }

    // epilogue: relu(h2 + b2) into smem (ring dead), then fused L3 head
    float* Cs = (float*)sm;
    __syncthreads();
#pragma unroll
    for (int mt = 0; mt < 2; mt++) {
        int r = warpM * 32 + mt * 16 + gid;
#pragma unroll
        for (int nt = 0; nt < 8; nt++) {
            int cc = warpN * 64 + nt * 8 + tig * 2;
            float bb0 = b2[e * H2D + cc];
            float bb1 = b2[e * H2D + cc + 1];
            Cs[r * CS_PITCH + cc]           = fmaxf(F.acc[mt][nt][0] + bb0, 0.f);
            Cs[r * CS_PITCH + cc + 1]       = fmaxf(F.acc[mt][nt][1] + bb1, 0.f);
            Cs[(r + 8) * CS_PITCH + cc]     = fmaxf(F.acc[mt][nt][2] + bb0, 0.f);
            Cs[(r + 8) * CS_PITCH + cc + 1] = fmaxf(F.acc[mt][nt][3] + bb1, 0.f);
        }
    }
    __syncthreads();

    for (int rr = 0; rr < 16; rr++) {
        int row = wid * 16 + rr;
        float p[EOUT];
#pragma unroll
        for (int o = 0; o < EOUT; o++) p[o] = 0.f;
#pragma unroll
        for (int q = 0; q < 4; q++) {
            float hv = Cs[row * CS_PITCH + q * 32 + lane];
            const float* w = &sW3[(q * 32 + lane) * EOUT];
#pragma unroll
            for (int o = 0; o < EOUT; o++) p[o] += hv * w[o];
        }
#pragma unroll
        for (int off = 16; off > 0; off >>= 1)
#pragma unroll
            for (int o = 0; o < EOUT; o++)
                p[o] += __shfl_down_sync(0xffffffffu, p[o], off);
        if (lane == 0) {
            float* dst = &g_eo[(size_t)(m0 + row) * (NE * EOUT) + e * EOUT];
#pragma unroll
            for (int o = 0; o < EOUT; o++) dst[o] = p[o] + sEb3[o];
        }
    }
}

// ================= gate (fp16 mma) + softmax + mmoe + avg + tower =================
// grid (ND, ceil(B/64)); A = gathered g_xh rows, B = g_gw1h[d].
__global__ __launch_bounds__(256, 2)
void gate_tower_mma(const float* __restrict__ Gb1,
                    const float* __restrict__ Gw2, const float* __restrict__ Gb2,
                    const float* __restrict__ Tw1, const float* __restrict__ Tb1,
                    const float* __restrict__ Tw2, const float* __restrict__ Tb2,
                    float* __restrict__ out)
{
    extern __shared__ uint32_t sm[];
    const uint32_t sbase = (uint32_t)__cvta_generic_to_shared(sm);
    const char* smc = (const char*)sm;
    // params region lives after the ring (persists through the GEMM)
    float* P     = (float*)((char*)sm + GRING_BYTES);
    float* sGw2  = P;                 // 384
    float* sGb2  = P + 384;           // 8
    float* sTw1  = P + 392;           // 640
    float* sTb1  = P + 1032;          // 64
    float* sTw2  = P + 1096;          // 64
    float* sGb1  = P + 1160;          // 64
    float* sTb2  = P + 1224;          // 1 (+pad)
    int*   sIdx  = (int*)(P + 1228);  // 64
    // gh aliases the ring (used only after the GEMM completes)
    float* gh = (float*)sm;           // [64][68]

    const int d    = blockIdx.x;
    const int base = blockIdx.y * 64;
    const int cnt  = g_cnt[d];
    if (base >= cnt) return;
    const int nrows = min(64, cnt - base);

    const int tid = threadIdx.x, lane = tid & 31, wid = tid >> 5;
    const int gid = lane >> 2, tig = lane & 3;
    const int warpM = wid & 3, warpN = wid >> 2;   // 4 x 2

    if (tid < 64)
        sIdx[tid] = (tid < nrows) ? g_idx[d * BATCH + base + tid]
                                  : g_idx[d * BATCH + base];
    for (int i = tid; i < GHID * NE; i += 256) sGw2[i] = Gw2[d * GHID * NE + i];
    if (tid < NE) sGb2[tid] = Gb2[d * NE + tid];
    for (int i = tid; i < EOUT * THID; i += 256) sTw1[i] = Tw1[d * EOUT * THID + i];
    if (tid < THID) {
        sTb1[tid] = Tb1[d * THID + tid];
        sTw2[tid] = Tw2[d * THID + tid];
        sGb1[tid] = Gb1[d * GHID + tid];
    }
    if (tid == 0) sTb2[0] = Tb2[d];
    __syncthreads();

    const __half* Bbase = g_gw1h + (size_t)d * GHID * IN_DIM;

    float acc[4][4];
#pragma unroll
    for (int nt = 0; nt < 4; nt++)
#pragma unroll
        for (int q = 0; q < 4; q++) acc[nt][q] = 0.f;

    auto gissue = [&](int stage, int c) {
        uint32_t sA = sbase + stage * GSTAGE_BYTES;
        uint32_t sB = sA + 4096;
        {   // A: 64 rows x 4 segs = 256 -> one per thread (gathered rows)
            int row = tid >> 2, cdx = tid & 3;
            cp_async16(sA + row * 64 + ((cdx ^ (row & 3)) << 4),
                       g_xh + (size_t)sIdx[row] * IN_DIM + c * 32 + cdx * 8);
        }
        {   // B: 64 rows x 4 segs = 256
            int row = tid >> 2, cdx = tid & 3;
            cp_async16(sB + row * 64 + ((cdx ^ (row & 3)) << 4),
                       Bbase + (size_t)row * IN_DIM + c * 32 + cdx * 8);
        }
    };

    constexpr int NC = IN_DIM / 32;   // 32
#pragma unroll
    for (int s = 0; s < NSTAGE - 1; s++) { gissue(s, s); CP_COMMIT(); }
#pragma unroll 1
    for (int c = 0; c < NC; c++) {
        cp_wait<NSTAGE - 2>();
        __syncthreads();
        int nxt = c + NSTAGE - 1;
        if (nxt < NC) gissue(nxt & (NSTAGE - 1), nxt);
        CP_COMMIT();
        const char* st = smc + (c & (NSTAGE - 1)) * GSTAGE_BYTES;
        uint4 Ar[2];
#pragma unroll
        for (int rr = 0; rr < 2; rr++) {
            int r = warpM * 16 + rr * 8 + gid;
            Ar[rr] = *(const uint4*)(st + r * 64 + ((tig ^ (r & 3)) << 4));
        }
#pragma unroll
        for (int nt = 0; nt < 4; nt++) {
            int n = warpN * 32 + nt * 8 + gid;
            uint4 Br = *(const uint4*)(st + 4096 + n * 64 + ((tig ^ (n & 3)) << 4));
            mma16(acc[nt], Ar[0].x, Ar[1].x, Ar[0].y, Ar[1].y, Br.x, Br.y);
            mma16(acc[nt], Ar[0].z, Ar[1].z, Ar[0].w, Ar[1].w, Br.z, Br.w);
        }
    }
    __syncthreads();   // ring dead; gh aliases it

    // write gh = relu(acc + Gb1)
#pragma unroll
    for (int nt = 0; nt < 4; nt++) {
        int cc = warpN * 32 + nt * 8 + tig * 2;
        int r0 = warpM * 16 + gid;
        float b0 = sGb1[cc], b1 = sGb1[cc + 1];
        gh[r0 * 68 + cc]           = fmaxf(acc[nt][0] + b0, 0.f);
        gh[r0 * 68 + cc + 1]       = fmaxf(acc[nt][1] + b1, 0.f);
        gh[(r0 + 8) * 68 + cc]     = fmaxf(acc[nt][2] + b0, 0.f);
        gh[(r0 + 8) * 68 + cc + 1] = fmaxf(acc[nt][3] + b1, 0.f);
    }
    __syncthreads();

    // per-sample epilogue: logits -> softmax -> mmoe -> tower
    if (tid < nrows) {
        const int m = tid;
        const int b = sIdx[m];

        float l[NE];
#pragma unroll
        for (int e = 0; e < NE; e++) l[e] = sGb2[e];
        for (int k = 0; k < GHID; k++) {
            float hv = gh[m * 68 + k];
#pragma unroll
            for (int e = 0; e < NE; e++) l[e] += hv * sGw2[k * NE + e];
        }
        float mx = l[0];
#pragma unroll
        for (int e = 1; e < NE; e++) mx = fmaxf(mx, l[e]);
        float ssum = 0.f;
#pragma unroll
        for (int e = 0; e < NE; e++) { l[e] = expf(l[e] - mx); ssum += l[e]; }
        float inv = 1.f / ssum;

        float mmoe[EOUT], avg[EOUT];
#pragma unroll
        for (int o = 0; o < EOUT; o++) { mmoe[o] = 0.f; avg[o] = 0.f; }
        const float* eorow = g_eo + (size_t)b * (NE * EOUT);
#pragma unroll
        for (int e = 0; e < NE; e++) {
            float gte = l[e] * inv;
#pragma unroll
            for (int o = 0; o < EOUT; o++) {
                float v = eorow[e * EOUT + o];
                mmoe[o] += gte * v;
                avg[o]  += v;
            }
        }
#pragma unroll
        for (int o = 0; o < EOUT; o++) {
            out[BATCH + (size_t)b * EOUT + o]      = avg[o] * (1.f / 6.f);
            out[11 * BATCH + (size_t)b * EOUT + o] = mmoe[o];
        }
        float tacc = sTb2[0];
        for (int h = 0; h < THID; h++) {
            float th = sTb1[h];
#pragma unroll
            for (int o = 0; o < EOUT; o++) th += mmoe[o] * sTw1[o * THID + h];
            th = fmaxf(th, 0.f);
            tacc += th * sTw2[h];
        }
        out[b] = 1.f / (1.f + expf(-tacc));
    }
}

// ------------------------------------------------------------------
extern "C" void kernel_launch(void* const* d_in, const int* in_sizes, int n_in,
                              void* d_out, int out_size)
{
    const float* x    = (const float*)d_in[0];
    const int*   dom  = (const int*)d_in[1];
    const float* Ew1  = (const float*)d_in[2];
    const float* Eb1  = (const float*)d_in[3];
    const float* Ew2  = (const float*)d_in[4];
    const float* Eb2  = (const float*)d_in[5];
    const float* Ew3  = (const float*)d_in[6];
    const float* Eb3  = (const float*)d_in[7];
    const float* Gw1  = (const float*)d_in[8];
    const float* Gb1  = (const float*)d_in[9];
    const float* Gw2  = (const float*)d_in[10];
    const float* Gb2  = (const float*)d_in[11];
    const float* Tw1  = (const float*)d_in[12];
    const float* Tb1  = (const float*)d_in[13];
    const float* Tw2  = (const float*)d_in[14];
    const float* Tb2  = (const float*)d_in[15];
    float* out = (float*)d_out;

    __half* w1h = nullptr; __half* w2h = nullptr; __half* gw1h = nullptr;
    cudaGetSymbolAddress((void**)&w1h,  g_w1h);
    cudaGetSymbolAddress((void**)&w2h,  g_w2h);
    cudaGetSymbolAddress((void**)&gw1h, g_gw1h);

    const int SMEM1 = RING_BYTES;                                   // 65536
    const int SMEM2 = 128 * CS_PITCH * 4 + (H2D * EOUT + 16) * 4;   // 72768
    const int SMEMG = GRING_BYTES + 1292 * 4 + 256;                 // ~38 KB
    cudaFuncSetAttribute(expert_l1_mma, cudaFuncAttributeMaxDynamicSharedMemorySize, SMEM1);
    cudaFuncSetAttribute(expert_l2_mma, cudaFuncAttributeMaxDynamicSharedMemorySize, SMEM2);
    cudaFuncSetAttribute(gate_tower_mma, cudaFuncAttributeMaxDynamicSharedMemorySize, SMEMG);

    zero_cnt_kernel<<<1, 32>>>();
    bucket_kernel<<<(BATCH + 255) / 256, 256>>>(dom);

    x_prep_kernel<<<(BATCH * IN_DIM / 8) / 256, 256>>>(x);
    w_prep_kernel<<<dim3(IN_DIM / 32, H1D / 32, NE), dim3(32, 8)>>>(Ew1, w1h, IN_DIM, H1D);
    w_prep_kernel<<<dim3(H1D / 32, H2D / 32, NE), dim3(32, 8)>>>(Ew2, w2h, H1D, H2D);
    w_prep_kernel<<<dim3(IN_DIM / 32, GHID / 32, ND), dim3(32, 8)>>>(Gw1, gw1h, IN_DIM, GHID);

    expert_l1_mma<<<dim3(BATCH / 128, 2, NE), 256, SMEM1>>>(Eb1);
    expert_l2_mma<<<dim3(BATCH / 128, 1, NE), 256, SMEM2>>>(Eb2, Ew3, Eb3);

    gate_tower_mma<<<dim3(ND, (BATCH + 63) / 64), 256, SMEMG>>>(
        Gb1, Gw2, Gb2, Tw1, Tb1, Tw2, Tb2, out);

    (void)in_sizes; (void)n_in; (void)out_size;
}

// round 8
// speedup vs baseline: 5.8517x; 1.0613x over previous
#include <cuda_runtime.h>
#include <cuda_fp16.h>
#include <cstdint>
#include <math.h>

#define BATCH   16384
#define IN_DIM  1024
#define NE      6
#define ND      20
#define H1D     256
#define H2D     128
#define EOUT    10
#define GHID    64
#define THID    64

// ---- scratch (device globals; no allocations allowed) ----
__device__ __half g_xh[BATCH * IN_DIM];        // fp16, k-permuted per 32-chunk (32 MB)
__device__ __half g_w1h[NE * H1D * IN_DIM];    // fp16, [e][n][k-perm]          (3 MB)
__device__ __half g_w2h[NE * H2D * H1D];       // fp16, [e][n][k-perm]          (384 KB)
__device__ __half g_gw1h[ND * GHID * IN_DIM];  // fp16, [d][n][k-perm]          (2.6 MB)
__device__ __half g_h1h[BATCH * NE * H1D];     // fp16, [m][e*256 + perm]       (50 MB)
__device__ float  g_eo[BATCH * NE * EOUT];     // fp32 [b][e][o]                (3.9 MB)
__device__ int    g_cnt[ND];
__device__ int    g_idx[ND * BATCH];

// ================= helpers =================
__device__ __forceinline__ uint32_t h2_as_u32(__half2 h) {
    return *(uint32_t*)&h;
}
// k-permutation within a 32-chunk: thread-in-group t (= (k&7)>>1) gets its 8
// needed halves {2t,2t+1, +8, +16, +24} contiguous -> one LDS.128 per K=32.
__device__ __host__ __forceinline__ int perm16(int k) {
    return ((k & 7) >> 1) * 8 + (k >> 3) * 2 + (k & 1);
}
__device__ __forceinline__ void mma16(float* c,
                                      uint32_t a0, uint32_t a1, uint32_t a2, uint32_t a3,
                                      uint32_t b0, uint32_t b1) {
    asm volatile(
        "mma.sync.aligned.m16n8k16.row.col.f32.f16.f16.f32 "
        "{%0,%1,%2,%3}, {%4,%5,%6,%7}, {%8,%9}, {%0,%1,%2,%3};"
        : "+f"(c[0]), "+f"(c[1]), "+f"(c[2]), "+f"(c[3])
        : "r"(a0), "r"(a1), "r"(a2), "r"(a3), "r"(b0), "r"(b1));
}
__device__ __forceinline__ void cp_async16(uint32_t saddr, const void* gptr) {
    asm volatile("cp.async.cg.shared.global [%0], [%1], 16;" :: "r"(saddr), "l"(gptr) : "memory");
}
#define CP_COMMIT() asm volatile("cp.async.commit_group;" ::: "memory")
template<int N> __device__ __forceinline__ void cp_wait() {
    asm volatile("cp.async.wait_group %0;" :: "n"(N) : "memory");
}

// Expert SMEM ring: K=64 stage = 2 subchunks x (A 8KB + B 8KB) = 32 KB; 3 stages.
#define SUB_BYTES   16384
#define ESTAGE_BYTES 32768
#define ENSTAGE     3
#define ERING_BYTES (ENSTAGE * ESTAGE_BYTES)     // 98304
// Gate SMEM ring: stage = A(64x64B) + B(64x64B) = 8 KB; 4 stages = 32 KB.
#define GSTAGE_BYTES 8192
#define GNSTAGE      4
#define GRING_BYTES  (GNSTAGE * GSTAGE_BYTES)

// ================= bucketing =================
__global__ void zero_cnt_kernel() {
    if (threadIdx.x < ND) g_cnt[threadIdx.x] = 0;
}
__global__ void bucket_kernel(const int* __restrict__ dom) {
    int b = blockIdx.x * blockDim.x + threadIdx.x;
    if (b < BATCH) {
        int d = dom[b];
        int p = atomicAdd(&g_cnt[d], 1);
        g_idx[d * BATCH + p] = b;
    }
}

// ================= prep: X -> fp16, k-permuted (8 elems/thread) =================
__global__ void x_prep_kernel(const float* __restrict__ X) {
    int idx = blockIdx.x * 256 + threadIdx.x;        // 2M threads
    int m = idx >> 7;
    int rest = idx & 127;
    int c = rest >> 2, t = rest & 3;                 // chunk, group
    const float* src = X + (size_t)m * IN_DIM + c * 32 + 2 * t;
    float2 v0 = *(const float2*)(src + 0);
    float2 v1 = *(const float2*)(src + 8);
    float2 v2 = *(const float2*)(src + 16);
    float2 v3 = *(const float2*)(src + 24);
    uint4 o;
    o.x = h2_as_u32(__floats2half2_rn(v0.x, v0.y));
    o.y = h2_as_u32(__floats2half2_rn(v1.x, v1.y));
    o.z = h2_as_u32(__floats2half2_rn(v2.x, v2.y));
    o.w = h2_as_u32(__floats2half2_rn(v3.x, v3.y));
    *(uint4*)(g_xh + (size_t)m * IN_DIM + c * 32 + t * 8) = o;
}

// ================= prep: W [e][K][N] -> [e][n][k-perm] fp16 =================
__global__ void w_prep_kernel(const float* __restrict__ W, __half* __restrict__ WT,
                              int K, int N) {
    __shared__ float tile[32][33];
    int e = blockIdx.z;
    int k0 = blockIdx.x * 32, n0 = blockIdx.y * 32;
    const float* Wp = W + (size_t)e * K * N;
    __half* Tp = WT + (size_t)e * N * K;
    int tx = threadIdx.x, ty = threadIdx.y;   // 32 x 8
#pragma unroll
    for (int j = 0; j < 32; j += 8)
        tile[ty + j][tx] = Wp[(size_t)(k0 + ty + j) * N + n0 + tx];
    __syncthreads();
#pragma unroll
    for (int j = 0; j < 32; j += 8)
        Tp[(size_t)(n0 + ty + j) * K + k0 + perm16(tx)] = __float2half_rn(tile[tx][ty + j]);
}

// ================= core tile ops (expert 128x128, K=64/stage) =================
struct Frag { float acc[2][8][4]; };

// issue one K=64 stage (two 32-k subchunks); 8 cp.async per thread
__device__ __forceinline__ void tile_issue64(uint32_t sbase, int stage, int tid,
                                             const __half* Ac, int ldA,
                                             const __half* Bc, int ldB)
{
#pragma unroll
    for (int sub = 0; sub < 2; sub++) {
        uint32_t sA = sbase + stage * ESTAGE_BYTES + sub * SUB_BYTES;
        uint32_t sB = sA + 8192;
        const __half* As = Ac + sub * 32;
        const __half* Bs = Bc + sub * 32;
#pragma unroll
        for (int i = 0; i < 2; i++) {
            int f = i * 256 + tid, row = f >> 2, cdx = f & 3;
            cp_async16(sA + row * 64 + ((cdx ^ (row & 3)) << 4),
                       As + (size_t)row * ldA + cdx * 8);
        }
#pragma unroll
        for (int i = 0; i < 2; i++) {
            int f = i * 256 + tid, row = f >> 2, cdx = f & 3;
            cp_async16(sB + row * 64 + ((cdx ^ (row & 3)) << 4),
                       Bs + (size_t)row * ldB + cdx * 8);
        }
    }
}

__device__ __forceinline__ void tile_compute64(const char* smc, int stage,
                                               int warpM, int warpN, int gid, int tig,
                                               Frag& F)
{
#pragma unroll
    for (int sub = 0; sub < 2; sub++) {
        const char* st = smc + stage * ESTAGE_BYTES + sub * SUB_BYTES;
        uint4 Ar[2][2];
#pragma unroll
        for (int mt = 0; mt < 2; mt++)
#pragma unroll
            for (int rr = 0; rr < 2; rr++) {
                int r = warpM * 32 + mt * 16 + rr * 8 + gid;
                Ar[mt][rr] = *(const uint4*)(st + r * 64 + ((tig ^ (r & 3)) << 4));
            }
#pragma unroll
        for (int nt = 0; nt < 8; nt++) {
            int n = warpN * 64 + nt * 8 + gid;
            uint4 Br = *(const uint4*)(st + 8192 + n * 64 + ((tig ^ (n & 3)) << 4));
#pragma unroll
            for (int mt = 0; mt < 2; mt++) {
                mma16(F.acc[mt][nt], Ar[mt][0].x, Ar[mt][1].x, Ar[mt][0].y, Ar[mt][1].y, Br.x, Br.y);
                mma16(F.acc[mt][nt], Ar[mt][0].z, Ar[mt][1].z, Ar[mt][0].w, Ar[mt][1].w, Br.z, Br.w);
            }
        }
    }
}

// ================= expert L1: fp16 mma GEMM (K=64 stages) =================
__global__ __launch_bounds__(256, 2)
void expert_l1_mma(const float* __restrict__ bias)
{
    extern __shared__ uint32_t sm[];
    const uint32_t sbase = (uint32_t)__cvta_generic_to_shared(sm);
    const char* smc = (const char*)sm;
    const int tid = threadIdx.x, lane = tid & 31, wid = tid >> 5;
    const int gid = lane >> 2, tig = lane & 3;
    const int warpM = wid & 3, warpN = wid >> 2;
    const int m0 = blockIdx.x * 128;
    const int n0 = blockIdx.y * 128;
    const int e  = blockIdx.z;
    const __half* Abase = g_xh + (size_t)m0 * IN_DIM;
    const __half* Bbase = g_w1h + (size_t)(e * H1D + n0) * IN_DIM;

    Frag F;
#pragma unroll
    for (int mt = 0; mt < 2; mt++)
#pragma unroll
        for (int nt = 0; nt < 8; nt++)
#pragma unroll
            for (int q = 0; q < 4; q++) F.acc[mt][nt][q] = 0.f;

    constexpr int NC = IN_DIM / 64;   // 16 stages of K=64
#pragma unroll
    for (int s = 0; s < ENSTAGE - 1; s++) {
        tile_issue64(sbase, s, tid, Abase + s * 64, IN_DIM, Bbase + s * 64, IN_DIM);
        CP_COMMIT();
    }
#pragma unroll 1
    for (int c = 0; c < NC; c++) {
        cp_wait<ENSTAGE - 2>();
        __syncthreads();
        int nxt = c + ENSTAGE - 1;
        if (nxt < NC)
            tile_issue64(sbase, nxt % ENSTAGE, tid,
                         Abase + nxt * 64, IN_DIM, Bbase + nxt * 64, IN_DIM);
        CP_COMMIT();
        tile_compute64(smc, c % ENSTAGE, warpM, warpN, gid, tig, F);
    }

    // epilogue: bias + relu -> fp16 permuted; one STG.128 per (mt,rr,cc)
#pragma unroll
    for (int mt = 0; mt < 2; mt++)
#pragma unroll
        for (int rr = 0; rr < 2; rr++) {
            int row = m0 + warpM * 32 + mt * 16 + rr * 8 + gid;
#pragma unroll
            for (int cc = 0; cc < 2; cc++) {
                uint32_t v[4];
#pragma unroll
                for (int q = 0; q < 4; q++) {
                    int nt = cc * 4 + q;
                    int nn = n0 + warpN * 64 + nt * 8 + tig * 2;
                    float b0 = bias[e * H1D + nn];
                    float b1 = bias[e * H1D + nn + 1];
                    v[q] = h2_as_u32(__floats2half2_rn(
                        fmaxf(F.acc[mt][nt][rr * 2 + 0] + b0, 0.f),
                        fmaxf(F.acc[mt][nt][rr * 2 + 1] + b1, 0.f)));
                }
                char* dst = (char*)g_h1h + (size_t)row * (NE * H1D * 2) + e * (H1D * 2)
                          + (size_t)(n0 / 32 + warpN * 2 + cc) * 64 + tig * 16;
                *(uint4*)dst = make_uint4(v[0], v[1], v[2], v[3]);
            }
        }
}

// ================= expert L2 (+fused L3): fp16 mma GEMM (K=64 stages) =================
#define CS_PITCH 132
__global__ __launch_bounds__(256, 2)
void expert_l2_mma(const float* __restrict__ b2, const float* __restrict__ W3,
                   const float* __restrict__ b3)
{
    extern __shared__ uint32_t sm[];
    const uint32_t sbase = (uint32_t)__cvta_generic_to_shared(sm);
    const char* smc = (const char*)sm;
    // params live AFTER the ring (ring is clobbered during GEMM, Cs after)
    float* sW3  = (float*)((char*)sm + ERING_BYTES);
    float* sEb3 = sW3 + H2D * EOUT;

    const int tid = threadIdx.x, lane = tid & 31, wid = tid >> 5;
    const int gid = lane >> 2, tig = lane & 3;
    const int warpM = wid & 3, warpN = wid >> 2;
    const int m0 = blockIdx.x * 128;
    const int e  = blockIdx.z;
    const __half* Abase = g_h1h + (size_t)m0 * (NE * H1D) + e * H1D;
    const __half* Bbase = g_w2h + (size_t)e * H2D * H1D;

    for (int i = tid; i < H2D * EOUT; i += 256) sW3[i] = W3[e * H2D * EOUT + i];
    if (tid < EOUT) sEb3[tid] = b3[e * EOUT + tid];

    Frag F;
#pragma unroll
    for (int mt = 0; mt < 2; mt++)
#pragma unroll
        for (int nt = 0; nt < 8; nt++)
#pragma unroll
            for (int q = 0; q < 4; q++) F.acc[mt][nt][q] = 0.f;

    constexpr int NC = H1D / 64;   // 4 stages of K=64
#pragma unroll
    for (int s = 0; s < ENSTAGE - 1; s++) {
        tile_issue64(sbase, s, tid, Abase + s * 64, NE * H1D, Bbase + s * 64, H1D);
        CP_COMMIT();
    }
#pragma unroll 1
    for (int c = 0; c < NC; c++) {
        cp_wait<ENSTAGE - 2>();
        __syncthreads();
        int nxt = c + ENSTAGE - 1;
        if (nxt < NC)
            tile_issue64(sbase, nxt % ENSTAGE, tid,
                         Abase + nxt * 64, NE * H1D, Bbase + nxt * 64, H1D);
        CP_COMMIT();
        tile_compute64(smc, c % ENSTAGE, warpM, warpN, gid, tig, F);
    }

    // epilogue: relu(h2 + b2) into smem (ring dead), then fused L3 head
    float* Cs = (float*)sm;
    __syncthreads();
#pragma unroll
    for (int mt = 0; mt < 2; mt++) {
        int r = warpM * 32 + mt * 16 + gid;
#pragma unroll
        for (int nt = 0; nt < 8; nt++) {
            int cc = warpN * 64 + nt * 8 + tig * 2;
            float bb0 = b2[e * H2D + cc];
            float bb1 = b2[e * H2D + cc + 1];
            Cs[r * CS_PITCH + cc]           = fmaxf(F.acc[mt][nt][0] + bb0, 0.f);
            Cs[r * CS_PITCH + cc + 1]       = fmaxf(F.acc[mt][nt][1] + bb1, 0.f);
            Cs[(r + 8) * CS_PITCH + cc]     = fmaxf(F.acc[mt][nt][2] + bb0, 0.f);
            Cs[(r + 8) * CS_PITCH + cc + 1] = fmaxf(F.acc[mt][nt][3] + bb1, 0.f);
        }
    }
    __syncthreads();

    for (int rr = 0; rr < 16; rr++) {
        int row = wid * 16 + rr;
        float p[EOUT];
#pragma unroll
        for (int o = 0; o < EOUT; o++) p[o] = 0.f;
#pragma unroll
        for (int q = 0; q < 4; q++) {
            float hv = Cs[row * CS_PITCH + q * 32 + lane];
            const float* w = &sW3[(q * 32 + lane) * EOUT];
#pragma unroll
            for (int o = 0; o < EOUT; o++) p[o] += hv * w[o];
        }
#pragma unroll
        for (int off = 16; off > 0; off >>= 1)
#pragma unroll
            for (int o = 0; o < EOUT; o++)
                p[o] += __shfl_down_sync(0xffffffffu, p[o], off);
        if (lane == 0) {
            float* dst = &g_eo[(size_t)(m0 + row) * (NE * EOUT) + e * EOUT];
#pragma unroll
            for (int o = 0; o < EOUT; o++) dst[o] = p[o] + sEb3[o];
        }
    }
}

// ================= gate (fp16 mma) + softmax + mmoe + avg + tower =================
__global__ __launch_bounds__(256, 2)
void gate_tower_mma(const float* __restrict__ Gb1,
                    const float* __restrict__ Gw2, const float* __restrict__ Gb2,
                    const float* __restrict__ Tw1, const float* __restrict__ Tb1,
                    const float* __restrict__ Tw2, const float* __restrict__ Tb2,
                    float* __restrict__ out)
{
    extern __shared__ uint32_t sm[];
    const uint32_t sbase = (uint32_t)__cvta_generic_to_shared(sm);
    const char* smc = (const char*)sm;
    float* P     = (float*)((char*)sm + GRING_BYTES);
    float* sGw2  = P;                 // 384
    float* sGb2  = P + 384;           // 8
    float* sTw1  = P + 392;           // 640
    float* sTb1  = P + 1032;          // 64
    float* sTw2  = P + 1096;          // 64
    float* sGb1  = P + 1160;          // 64
    float* sTb2  = P + 1224;          // 1 (+pad)
    int*   sIdx  = (int*)(P + 1228);  // 64
    float* gh = (float*)sm;           // [64][68], aliases ring after GEMM

    const int d    = blockIdx.x;
    const int base = blockIdx.y * 64;
    const int cnt  = g_cnt[d];
    if (base >= cnt) return;
    const int nrows = min(64, cnt - base);

    const int tid = threadIdx.x, lane = tid & 31, wid = tid >> 5;
    const int gid = lane >> 2, tig = lane & 3;
    const int warpM = wid & 3, warpN = wid >> 2;   // 4 x 2

    if (tid < 64)
        sIdx[tid] = (tid < nrows) ? g_idx[d * BATCH + base + tid]
                                  : g_idx[d * BATCH + base];
    for (int i = tid; i < GHID * NE; i += 256) sGw2[i] = Gw2[d * GHID * NE + i];
    if (tid < NE) sGb2[tid] = Gb2[d * NE + tid];
    for (int i = tid; i < EOUT * THID; i += 256) sTw1[i] = Tw1[d * EOUT * THID + i];
    if (tid < THID) {
        sTb1[tid] = Tb1[d * THID + tid];
        sTw2[tid] = Tw2[d * THID + tid];
        sGb1[tid] = Gb1[d * GHID + tid];
    }
    if (tid == 0) sTb2[0] = Tb2[d];
    __syncthreads();

    const __half* Bbase = g_gw1h + (size_t)d * GHID * IN_DIM;

    float acc[4][4];
#pragma unroll
    for (int nt = 0; nt < 4; nt++)
#pragma unroll
        for (int q = 0; q < 4; q++) acc[nt][q] = 0.f;

    auto gissue = [&](int stage, int c) {
        uint32_t sA = sbase + stage * GSTAGE_BYTES;
        uint32_t sB = sA + 4096;
        {
            int row = tid >> 2, cdx = tid & 3;
            cp_async16(sA + row * 64 + ((cdx ^ (row & 3)) << 4),
                       g_xh + (size_t)sIdx[row] * IN_DIM + c * 32 + cdx * 8);
        }
        {
            int row = tid >> 2, cdx = tid & 3;
            cp_async16(sB + row * 64 + ((cdx ^ (row & 3)) << 4),
                       Bbase + (size_t)row * IN_DIM + c * 32 + cdx * 8);
        }
    };

    constexpr int NC = IN_DIM / 32;   // 32
#pragma unroll
    for (int s = 0; s < GNSTAGE - 1; s++) { gissue(s, s); CP_COMMIT(); }
#pragma unroll 1
    for (int c = 0; c < NC; c++) {
        cp_wait<GNSTAGE - 2>();
        __syncthreads();
        int nxt = c + GNSTAGE - 1;
        if (nxt < NC) gissue(nxt & (GNSTAGE - 1), nxt);
        CP_COMMIT();
        const char* st = smc + (c & (GNSTAGE - 1)) * GSTAGE_BYTES;
        uint4 Ar[2];
#pragma unroll
        for (int rr = 0; rr < 2; rr++) {
            int r = warpM * 16 + rr * 8 + gid;
            Ar[rr] = *(const uint4*)(st + r * 64 + ((tig ^ (r & 3)) << 4));
        }
#pragma unroll
        for (int nt = 0; nt < 4; nt++) {
            int n = warpN * 32 + nt * 8 + gid;
            uint4 Br = *(const uint4*)(st + 4096 + n * 64 + ((tig ^ (n & 3)) << 4));
            mma16(acc[nt], Ar[0].x, Ar[1].x, Ar[0].y, Ar[1].y, Br.x, Br.y);
            mma16(acc[nt], Ar[0].z, Ar[1].z, Ar[0].w, Ar[1].w, Br.z, Br.w);
        }
    }
    __syncthreads();   // ring dead; gh aliases it

#pragma unroll
    for (int nt = 0; nt < 4; nt++) {
        int cc = warpN * 32 + nt * 8 + tig * 2;
        int r0 = warpM * 16 + gid;
        float b0 = sGb1[cc], b1 = sGb1[cc + 1];
        gh[r0 * 68 + cc]           = fmaxf(acc[nt][0] + b0, 0.f);
        gh[r0 * 68 + cc + 1]       = fmaxf(acc[nt][1] + b1, 0.f);
        gh[(r0 + 8) * 68 + cc]     = fmaxf(acc[nt][2] + b0, 0.f);
        gh[(r0 + 8) * 68 + cc + 1] = fmaxf(acc[nt][3] + b1, 0.f);
    }
    __syncthreads();

    if (tid < nrows) {
        const int m = tid;
        const int b = sIdx[m];

        float l[NE];
#pragma unroll
        for (int e = 0; e < NE; e++) l[e] = sGb2[e];
        for (int k = 0; k < GHID; k++) {
            float hv = gh[m * 68 + k];
#pragma unroll
            for (int e = 0; e < NE; e++) l[e] += hv * sGw2[k * NE + e];
        }
        float mx = l[0];
#pragma unroll
        for (int e = 1; e < NE; e++) mx = fmaxf(mx, l[e]);
        float ssum = 0.f;
#pragma unroll
        for (int e = 0; e < NE; e++) { l[e] = expf(l[e] - mx); ssum += l[e]; }
        float inv = 1.f / ssum;

        float mmoe[EOUT], avg[EOUT];
#pragma unroll
        for (int o = 0; o < EOUT; o++) { mmoe[o] = 0.f; avg[o] = 0.f; }
        const float* eorow = g_eo + (size_t)b * (NE * EOUT);
#pragma unroll
        for (int e = 0; e < NE; e++) {
            float gte = l[e] * inv;
#pragma unroll
            for (int o = 0; o < EOUT; o++) {
                float v = eorow[e * EOUT + o];
                mmoe[o] += gte * v;
                avg[o]  += v;
            }
        }
#pragma unroll
        for (int o = 0; o < EOUT; o++) {
            out[BATCH + (size_t)b * EOUT + o]      = avg[o] * (1.f / 6.f);
            out[11 * BATCH + (size_t)b * EOUT + o] = mmoe[o];
        }
        float tacc = sTb2[0];
        for (int h = 0; h < THID; h++) {
            float th = sTb1[h];
#pragma unroll
            for (int o = 0; o < EOUT; o++) th += mmoe[o] * sTw1[o * THID + h];
            th = fmaxf(th, 0.f);
            tacc += th * sTw2[h];
        }
        out[b] = 1.f / (1.f + expf(-tacc));
    }
}

// ------------------------------------------------------------------
extern "C" void kernel_launch(void* const* d_in, const int* in_sizes, int n_in,
                              void* d_out, int out_size)
{
    const float* x    = (const float*)d_in[0];
    const int*   dom  = (const int*)d_in[1];
    const float* Ew1  = (const float*)d_in[2];
    const float* Eb1  = (const float*)d_in[3];
    const float* Ew2  = (const float*)d_in[4];
    const float* Eb2  = (const float*)d_in[5];
    const float* Ew3  = (const float*)d_in[6];
    const float* Eb3  = (const float*)d_in[7];
    const float* Gw1  = (const float*)d_in[8];
    const float* Gb1  = (const float*)d_in[9];
    const float* Gw2  = (const float*)d_in[10];
    const float* Gb2  = (const float*)d_in[11];
    const float* Tw1  = (const float*)d_in[12];
    const float* Tb1  = (const float*)d_in[13];
    const float* Tw2  = (const float*)d_in[14];
    const float* Tb2  = (const float*)d_in[15];
    float* out = (float*)d_out;

    __half* w1h = nullptr; __half* w2h = nullptr; __half* gw1h = nullptr;
    cudaGetSymbolAddress((void**)&w1h,  g_w1h);
    cudaGetSymbolAddress((void**)&w2h,  g_w2h);
    cudaGetSymbolAddress((void**)&gw1h, g_gw1h);

    const int SMEM1 = ERING_BYTES;                                  // 98304
    const int SMEM2 = ERING_BYTES + (H2D * EOUT + 16) * 4;          // 103488
    const int SMEMG = GRING_BYTES + 1292 * 4 + 256;                 // ~38 KB
    cudaFuncSetAttribute(expert_l1_mma, cudaFuncAttributeMaxDynamicSharedMemorySize, SMEM1);
    cudaFuncSetAttribute(expert_l2_mma, cudaFuncAttributeMaxDynamicSharedMemorySize, SMEM2);
    cudaFuncSetAttribute(gate_tower_mma, cudaFuncAttributeMaxDynamicSharedMemorySize, SMEMG);

    zero_cnt_kernel<<<1, 32>>>();
    bucket_kernel<<<(BATCH + 255) / 256, 256>>>(dom);

    x_prep_kernel<<<(BATCH * IN_DIM / 8) / 256, 256>>>(x);
    w_prep_kernel<<<dim3(IN_DIM / 32, H1D / 32, NE), dim3(32, 8)>>>(Ew1, w1h, IN_DIM, H1D);
    w_prep_kernel<<<dim3(H1D / 32, H2D / 32, NE), dim3(32, 8)>>>(Ew2, w2h, H1D, H2D);
    w_prep_kernel<<<dim3(IN_DIM / 32, GHID / 32, ND), dim3(32, 8)>>>(Gw1, gw1h, IN_DIM, GHID);

    expert_l1_mma<<<dim3(BATCH / 128, 2, NE), 256, SMEM1>>>(Eb1);
    expert_l2_mma<<<dim3(BATCH / 128, 1, NE), 256, SMEM2>>>(Eb2, Ew3, Eb3);

    gate_tower_mma<<<dim3(ND, (BATCH + 63) / 64), 256, SMEMG>>>(
        Gb1, Gw2, Gb2, Tw1, Tb1, Tw2, Tb2, out);

    (void)in_sizes; (void)n_in; (void)out_size;
}

// round 9
// speedup vs baseline: 5.9824x; 1.0223x over previous
#include <cuda_runtime.h>
#include <cuda_fp16.h>
#include <cstdint>
#include <math.h>

#define BATCH   16384
#define IN_DIM  1024
#define NE      6
#define ND      20
#define H1D     256
#define H2D     128
#define EOUT    10
#define GHID    64
#define THID    64

// ---- scratch (device globals; no allocations allowed) ----
__device__ __half g_xh[BATCH * IN_DIM];        // fp16, k-permuted per 32-chunk (32 MB)
__device__ __half g_w1h[NE * H1D * IN_DIM];    // fp16, [e][n][k-perm]          (3 MB)
__device__ __half g_w2h[NE * H2D * H1D];       // fp16, [e][n][k-perm]          (384 KB)
__device__ __half g_gw1h[ND * GHID * IN_DIM];  // fp16, [d][n][k-perm]          (2.6 MB)
__device__ __half g_h1h[BATCH * NE * H1D];     // fp16, [m][e*256 + perm]       (50 MB)
__device__ float  g_eo[BATCH * NE * EOUT];     // fp32 [b][e][o]                (3.9 MB)
__device__ int    g_cnt[ND];
__device__ int    g_idx[ND * BATCH];

// ================= helpers =================
__device__ __forceinline__ uint32_t h2_as_u32(__half2 h) {
    return *(uint32_t*)&h;
}
// k-permutation within a 32-chunk: thread-in-group t (= (k&7)>>1) gets its 8
// needed halves {2t,2t+1, +8, +16, +24} contiguous -> one 16B LDG per K=32.
__device__ __host__ __forceinline__ int perm16(int k) {
    return ((k & 7) >> 1) * 8 + (k >> 3) * 2 + (k & 1);
}
__device__ __forceinline__ void mma16(float* c,
                                      uint32_t a0, uint32_t a1, uint32_t a2, uint32_t a3,
                                      uint32_t b0, uint32_t b1) {
    asm volatile(
        "mma.sync.aligned.m16n8k16.row.col.f32.f16.f16.f32 "
        "{%0,%1,%2,%3}, {%4,%5,%6,%7}, {%8,%9}, {%0,%1,%2,%3};"
        : "+f"(c[0]), "+f"(c[1]), "+f"(c[2]), "+f"(c[3])
        : "r"(a0), "r"(a1), "r"(a2), "r"(a3), "r"(b0), "r"(b1));
}

// ================= bucketing =================
__global__ void zero_cnt_kernel() {
    if (threadIdx.x < ND) g_cnt[threadIdx.x] = 0;
}
__global__ void bucket_kernel(const int* __restrict__ dom) {
    int b = blockIdx.x * blockDim.x + threadIdx.x;
    if (b < BATCH) {
        int d = dom[b];
        int p = atomicAdd(&g_cnt[d], 1);
        g_idx[d * BATCH + p] = b;
    }
}

// ================= prep: X -> fp16, k-permuted (8 elems/thread) =================
__global__ void x_prep_kernel(const float* __restrict__ X) {
    int idx = blockIdx.x * 256 + threadIdx.x;        // 2M threads
    int m = idx >> 7;
    int rest = idx & 127;
    int c = rest >> 2, t = rest & 3;                 // chunk, group
    const float* src = X + (size_t)m * IN_DIM + c * 32 + 2 * t;
    float2 v0 = *(const float2*)(src + 0);
    float2 v1 = *(const float2*)(src + 8);
    float2 v2 = *(const float2*)(src + 16);
    float2 v3 = *(const float2*)(src + 24);
    uint4 o;
    o.x = h2_as_u32(__floats2half2_rn(v0.x, v0.y));
    o.y = h2_as_u32(__floats2half2_rn(v1.x, v1.y));
    o.z = h2_as_u32(__floats2half2_rn(v2.x, v2.y));
    o.w = h2_as_u32(__floats2half2_rn(v3.x, v3.y));
    *(uint4*)(g_xh + (size_t)m * IN_DIM + c * 32 + t * 8) = o;
}

// ================= prep: W [e][K][N] -> [e][n][k-perm] fp16 =================
__global__ void w_prep_kernel(const float* __restrict__ W, __half* __restrict__ WT,
                              int K, int N) {
    __shared__ float tile[32][33];
    int e = blockIdx.z;
    int k0 = blockIdx.x * 32, n0 = blockIdx.y * 32;
    const float* Wp = W + (size_t)e * K * N;
    __half* Tp = WT + (size_t)e * N * K;
    int tx = threadIdx.x, ty = threadIdx.y;   // 32 x 8
#pragma unroll
    for (int j = 0; j < 32; j += 8)
        tile[ty + j][tx] = Wp[(size_t)(k0 + ty + j) * N + n0 + tx];
    __syncthreads();
#pragma unroll
    for (int j = 0; j < 32; j += 8)
        Tp[(size_t)(n0 + ty + j) * K + k0 + perm16(tx)] = __float2half_rn(tile[tx][ty + j]);
}

// ================= expert L1: direct-LDG fp16 mma GEMM (no SMEM) =================
// grid (128, 2, 6). Fragments loaded straight from permuted global layout.
__global__ __launch_bounds__(256, 2)
void expert_l1_mma(const float* __restrict__ bias)
{
    const int tid = threadIdx.x, lane = tid & 31, wid = tid >> 5;
    const int gid = lane >> 2, tig = lane & 3;
    const int warpM = wid & 3, warpN = wid >> 2;
    const int m0 = blockIdx.x * 128;
    const int n0 = blockIdx.y * 128;
    const int e  = blockIdx.z;

    // per-thread fragment base pointers (16B segments, warp-coalesced)
    const __half* Ap = g_xh + (size_t)(m0 + warpM * 32 + gid) * IN_DIM + tig * 8;
    const __half* Bp = g_w1h + (size_t)(e * H1D + n0 + warpN * 64 + gid) * IN_DIM + tig * 8;

    float acc[2][8][4];
#pragma unroll
    for (int mt = 0; mt < 2; mt++)
#pragma unroll
        for (int nt = 0; nt < 8; nt++)
#pragma unroll
            for (int q = 0; q < 4; q++) acc[mt][nt][q] = 0.f;

#pragma unroll 2
    for (int c = 0; c < IN_DIM / 32; c++) {
        const __half* Ac = Ap + c * 32;
        const __half* Bc = Bp + c * 32;
        uint4 Ar[2][2];
#pragma unroll
        for (int mt = 0; mt < 2; mt++)
#pragma unroll
            for (int rr = 0; rr < 2; rr++)
                Ar[mt][rr] = *(const uint4*)(Ac + (mt * 16 + rr * 8) * IN_DIM);
#pragma unroll
        for (int nt = 0; nt < 8; nt++) {
            uint4 Br = *(const uint4*)(Bc + nt * 8 * IN_DIM);
#pragma unroll
            for (int mt = 0; mt < 2; mt++) {
                mma16(acc[mt][nt], Ar[mt][0].x, Ar[mt][1].x, Ar[mt][0].y, Ar[mt][1].y, Br.x, Br.y);
                mma16(acc[mt][nt], Ar[mt][0].z, Ar[mt][1].z, Ar[mt][0].w, Ar[mt][1].w, Br.z, Br.w);
            }
        }
    }

    // epilogue: bias + relu -> fp16 permuted; one STG.128 per (mt,rr,cc)
#pragma unroll
    for (int mt = 0; mt < 2; mt++)
#pragma unroll
        for (int rr = 0; rr < 2; rr++) {
            int row = m0 + warpM * 32 + mt * 16 + rr * 8 + gid;
#pragma unroll
            for (int cc = 0; cc < 2; cc++) {
                uint32_t v[4];
#pragma unroll
                for (int q = 0; q < 4; q++) {
                    int nt = cc * 4 + q;
                    int nn = n0 + warpN * 64 + nt * 8 + tig * 2;
                    float b0 = bias[e * H1D + nn];
                    float b1 = bias[e * H1D + nn + 1];
                    v[q] = h2_as_u32(__floats2half2_rn(
                        fmaxf(acc[mt][nt][rr * 2 + 0] + b0, 0.f),
                        fmaxf(acc[mt][nt][rr * 2 + 1] + b1, 0.f)));
                }
                char* dst = (char*)g_h1h + (size_t)row * (NE * H1D * 2) + e * (H1D * 2)
                          + (size_t)(n0 / 32 + warpN * 2 + cc) * 64 + tig * 16;
                *(uint4*)dst = make_uint4(v[0], v[1], v[2], v[3]);
            }
        }
}

// ================= expert L2 (+fused L3): direct-LDG fp16 mma GEMM =================
#define CS_PITCH 132
__global__ __launch_bounds__(256, 2)
void expert_l2_mma(const float* __restrict__ b2, const float* __restrict__ W3,
                   const float* __restrict__ b3)
{
    extern __shared__ uint32_t sm[];
    float* Cs   = (float*)sm;                          // [128][132] epilogue buffer
    float* sW3  = (float*)((char*)sm + 128 * CS_PITCH * 4);
    float* sEb3 = sW3 + H2D * EOUT;

    const int tid = threadIdx.x, lane = tid & 31, wid = tid >> 5;
    const int gid = lane >> 2, tig = lane & 3;
    const int warpM = wid & 3, warpN = wid >> 2;
    const int m0 = blockIdx.x * 128;
    const int e  = blockIdx.z;

    for (int i = tid; i < H2D * EOUT; i += 256) sW3[i] = W3[e * H2D * EOUT + i];
    if (tid < EOUT) sEb3[tid] = b3[e * EOUT + tid];

    const __half* Ap = g_h1h + (size_t)(m0 + warpM * 32 + gid) * (NE * H1D) + e * H1D + tig * 8;
    const __half* Bp = g_w2h + (size_t)(e * H2D + warpN * 64 + gid) * H1D + tig * 8;

    float acc[2][8][4];
#pragma unroll
    for (int mt = 0; mt < 2; mt++)
#pragma unroll
        for (int nt = 0; nt < 8; nt++)
#pragma unroll
            for (int q = 0; q < 4; q++) acc[mt][nt][q] = 0.f;

#pragma unroll
    for (int c = 0; c < H1D / 32; c++) {
        const __half* Ac = Ap + c * 32;
        const __half* Bc = Bp + c * 32;
        uint4 Ar[2][2];
#pragma unroll
        for (int mt = 0; mt < 2; mt++)
#pragma unroll
            for (int rr = 0; rr < 2; rr++)
                Ar[mt][rr] = *(const uint4*)(Ac + (mt * 16 + rr * 8) * (NE * H1D));
#pragma unroll
        for (int nt = 0; nt < 8; nt++) {
            uint4 Br = *(const uint4*)(Bc + nt * 8 * H1D);
#pragma unroll
            for (int mt = 0; mt < 2; mt++) {
                mma16(acc[mt][nt], Ar[mt][0].x, Ar[mt][1].x, Ar[mt][0].y, Ar[mt][1].y, Br.x, Br.y);
                mma16(acc[mt][nt], Ar[mt][0].z, Ar[mt][1].z, Ar[mt][0].w, Ar[mt][1].w, Br.z, Br.w);
            }
        }
    }

    // epilogue: relu(h2 + b2) into smem, then fused L3 head
    __syncthreads();
#pragma unroll
    for (int mt = 0; mt < 2; mt++) {
        int r = warpM * 32 + mt * 16 + gid;
#pragma unroll
        for (int nt = 0; nt < 8; nt++) {
            int cc = warpN * 64 + nt * 8 + tig * 2;
            float bb0 = b2[e * H2D + cc];
            float bb1 = b2[e * H2D + cc + 1];
            Cs[r * CS_PITCH + cc]           = fmaxf(acc[mt][nt][0] + bb0, 0.f);
            Cs[r * CS_PITCH + cc + 1]       = fmaxf(acc[mt][nt][1] + bb1, 0.f);
            Cs[(r + 8) * CS_PITCH + cc]     = fmaxf(acc[mt][nt][2] + bb0, 0.f);
            Cs[(r + 8) * CS_PITCH + cc + 1] = fmaxf(acc[mt][nt][3] + bb1, 0.f);
        }
    }
    __syncthreads();

    for (int rr = 0; rr < 16; rr++) {
        int row = wid * 16 + rr;
        float p[EOUT];
#pragma unroll
        for (int o = 0; o < EOUT; o++) p[o] = 0.f;
#pragma unroll
        for (int q = 0; q < 4; q++) {
            float hv = Cs[row * CS_PITCH + q * 32 + lane];
            const float* w = &sW3[(q * 32 + lane) * EOUT];
#pragma unroll
            for (int o = 0; o < EOUT; o++) p[o] += hv * w[o];
        }
#pragma unroll
        for (int off = 16; off > 0; off >>= 1)
#pragma unroll
            for (int o = 0; o < EOUT; o++)
                p[o] += __shfl_down_sync(0xffffffffu, p[o], off);
        if (lane == 0) {
            float* dst = &g_eo[(size_t)(m0 + row) * (NE * EOUT) + e * EOUT];
#pragma unroll
            for (int o = 0; o < EOUT; o++) dst[o] = p[o] + sEb3[o];
        }
    }
}

// ================= gate (direct-LDG fp16 mma) + softmax + mmoe + avg + tower ===
__global__ __launch_bounds__(256, 2)
void gate_tower_mma(const float* __restrict__ Gb1,
                    const float* __restrict__ Gw2, const float* __restrict__ Gb2,
                    const float* __restrict__ Tw1, const float* __restrict__ Tb1,
                    const float* __restrict__ Tw2, const float* __restrict__ Tb2,
                    float* __restrict__ out)
{
    extern __shared__ uint32_t sm[];
    float* gh = (float*)sm;                            // [64][68]
    float* P     = (float*)((char*)sm + 64 * 68 * 4);
    float* sGw2  = P;                 // 384
    float* sGb2  = P + 384;           // 8
    float* sTw1  = P + 392;           // 640
    float* sTb1  = P + 1032;          // 64
    float* sTw2  = P + 1096;          // 64
    float* sGb1  = P + 1160;          // 64
    float* sTb2  = P + 1224;          // 1 (+pad)
    int*   sIdx  = (int*)(P + 1228);  // 64

    const int d    = blockIdx.x;
    const int base = blockIdx.y * 64;
    const int cnt  = g_cnt[d];
    if (base >= cnt) return;
    const int nrows = min(64, cnt - base);

    const int tid = threadIdx.x, lane = tid & 31, wid = tid >> 5;
    const int gid = lane >> 2, tig = lane & 3;
    const int warpM = wid & 3, warpN = wid >> 2;   // 4 x 2

    if (tid < 64)
        sIdx[tid] = (tid < nrows) ? g_idx[d * BATCH + base + tid]
                                  : g_idx[d * BATCH + base];
    for (int i = tid; i < GHID * NE; i += 256) sGw2[i] = Gw2[d * GHID * NE + i];
    if (tid < NE) sGb2[tid] = Gb2[d * NE + tid];
    for (int i = tid; i < EOUT * THID; i += 256) sTw1[i] = Tw1[d * EOUT * THID + i];
    if (tid < THID) {
        sTb1[tid] = Tb1[d * THID + tid];
        sTw2[tid] = Tw2[d * THID + tid];
        sGb1[tid] = Gb1[d * GHID + tid];
    }
    if (tid == 0) sTb2[0] = Tb2[d];
    __syncthreads();

    // per-thread gathered A pointers + B pointer
    const __half* Ap0 = g_xh + (size_t)sIdx[warpM * 16 + gid] * IN_DIM + tig * 8;
    const __half* Ap1 = g_xh + (size_t)sIdx[warpM * 16 + 8 + gid] * IN_DIM + tig * 8;
    const __half* Bp  = g_gw1h + (size_t)(d * GHID + warpN * 32 + gid) * IN_DIM + tig * 8;

    float acc[4][4];
#pragma unroll
    for (int nt = 0; nt < 4; nt++)
#pragma unroll
        for (int q = 0; q < 4; q++) acc[nt][q] = 0.f;

#pragma unroll 2
    for (int c = 0; c < IN_DIM / 32; c++) {
        uint4 A0 = *(const uint4*)(Ap0 + c * 32);
        uint4 A1 = *(const uint4*)(Ap1 + c * 32);
#pragma unroll
        for (int nt = 0; nt < 4; nt++) {
            uint4 Br = *(const uint4*)(Bp + nt * 8 * IN_DIM + c * 32);
            mma16(acc[nt], A0.x, A1.x, A0.y, A1.y, Br.x, Br.y);
            mma16(acc[nt], A0.z, A1.z, A0.w, A1.w, Br.z, Br.w);
        }
    }

    // gh = relu(acc + Gb1)
#pragma unroll
    for (int nt = 0; nt < 4; nt++) {
        int cc = warpN * 32 + nt * 8 + tig * 2;
        int r0 = warpM * 16 + gid;
        float b0 = sGb1[cc], b1 = sGb1[cc + 1];
        gh[r0 * 68 + cc]           = fmaxf(acc[nt][0] + b0, 0.f);
        gh[r0 * 68 + cc + 1]       = fmaxf(acc[nt][1] + b1, 0.f);
        gh[(r0 + 8) * 68 + cc]     = fmaxf(acc[nt][2] + b0, 0.f);
        gh[(r0 + 8) * 68 + cc + 1] = fmaxf(acc[nt][3] + b1, 0.f);
    }
    __syncthreads();

    // per-sample epilogue: logits -> softmax -> mmoe -> tower
    if (tid < nrows) {
        const int m = tid;
        const int b = sIdx[m];

        float l[NE];
#pragma unroll
        for (int e = 0; e < NE; e++) l[e] = sGb2[e];
        for (int k = 0; k < GHID; k++) {
            float hv = gh[m * 68 + k];
#pragma unroll
            for (int e = 0; e < NE; e++) l[e] += hv * sGw2[k * NE + e];
        }
        float mx = l[0];
#pragma unroll
        for (int e = 1; e < NE; e++) mx = fmaxf(mx, l[e]);
        float ssum = 0.f;
#pragma unroll
        for (int e = 0; e < NE; e++) { l[e] = expf(l[e] - mx); ssum += l[e]; }
        float inv = 1.f / ssum;

        float mmoe[EOUT], avg[EOUT];
#pragma unroll
        for (int o = 0; o < EOUT; o++) { mmoe[o] = 0.f; avg[o] = 0.f; }
        const float* eorow = g_eo + (size_t)b * (NE * EOUT);
#pragma unroll
        for (int e = 0; e < NE; e++) {
            float gte = l[e] * inv;
#pragma unroll
            for (int o = 0; o < EOUT; o++) {
                float v = eorow[e * EOUT + o];
                mmoe[o] += gte * v;
                avg[o]  += v;
            }
        }
#pragma unroll
        for (int o = 0; o < EOUT; o++) {
            out[BATCH + (size_t)b * EOUT + o]      = avg[o] * (1.f / 6.f);
            out[11 * BATCH + (size_t)b * EOUT + o] = mmoe[o];
        }
        float tacc = sTb2[0];
        for (int h = 0; h < THID; h++) {
            float th = sTb1[h];
#pragma unroll
            for (int o = 0; o < EOUT; o++) th += mmoe[o] * sTw1[o * THID + h];
            th = fmaxf(th, 0.f);
            tacc += th * sTw2[h];
        }
        out[b] = 1.f / (1.f + expf(-tacc));
    }
}

// ------------------------------------------------------------------
extern "C" void kernel_launch(void* const* d_in, const int* in_sizes, int n_in,
                              void* d_out, int out_size)
{
    const float* x    = (const float*)d_in[0];
    const int*   dom  = (const int*)d_in[1];
    const float* Ew1  = (const float*)d_in[2];
    const float* Eb1  = (const float*)d_in[3];
    const float* Ew2  = (const float*)d_in[4];
    const float* Eb2  = (const float*)d_in[5];
    const float* Ew3  = (const float*)d_in[6];
    const float* Eb3  = (const float*)d_in[7];
    const float* Gw1  = (const float*)d_in[8];
    const float* Gb1  = (const float*)d_in[9];
    const float* Gw2  = (const float*)d_in[10];
    const float* Gb2  = (const float*)d_in[11];
    const float* Tw1  = (const float*)d_in[12];
    const float* Tb1  = (const float*)d_in[13];
    const float* Tw2  = (const float*)d_in[14];
    const float* Tb2  = (const float*)d_in[15];
    float* out = (float*)d_out;

    __half* w1h = nullptr; __half* w2h = nullptr; __half* gw1h = nullptr;
    cudaGetSymbolAddress((void**)&w1h,  g_w1h);
    cudaGetSymbolAddress((void**)&w2h,  g_w2h);
    cudaGetSymbolAddress((void**)&gw1h, g_gw1h);

    const int SMEM2 = 128 * CS_PITCH * 4 + (H2D * EOUT + 16) * 4;   // 72768
    const int SMEMG = 64 * 68 * 4 + 1292 * 4 + 256;                 // ~23 KB
    cudaFuncSetAttribute(expert_l2_mma, cudaFuncAttributeMaxDynamicSharedMemorySize, SMEM2);
    cudaFuncSetAttribute(gate_tower_mma, cudaFuncAttributeMaxDynamicSharedMemorySize, SMEMG);

    // launch order chosen so ncu (-s 5 -c 1) captures expert_l1_mma
    zero_cnt_kernel<<<1, 32>>>();                                           // 0
    bucket_kernel<<<(BATCH + 255) / 256, 256>>>(dom);                       // 1
    x_prep_kernel<<<(BATCH * IN_DIM / 8) / 256, 256>>>(x);                  // 2
    w_prep_kernel<<<dim3(IN_DIM / 32, H1D / 32, NE), dim3(32, 8)>>>(Ew1, w1h, IN_DIM, H1D);  // 3
    w_prep_kernel<<<dim3(H1D / 32, H2D / 32, NE), dim3(32, 8)>>>(Ew2, w2h, H1D, H2D);        // 4
    expert_l1_mma<<<dim3(BATCH / 128, 2, NE), 256>>>(Eb1);                  // 5 <- profiled
    w_prep_kernel<<<dim3(IN_DIM / 32, GHID / 32, ND), dim3(32, 8)>>>(Gw1, gw1h, IN_DIM, GHID); // 6
    expert_l2_mma<<<dim3(BATCH / 128, 1, NE), 256, SMEM2>>>(Eb2, Ew3, Eb3); // 7
    gate_tower_mma<<<dim3(ND, (BATCH + 63) / 64), 256, SMEMG>>>(            // 8
        Gb1, Gw2, Gb2, Tw1, Tb1, Tw2, Tb2, out);

    (void)in_sizes; (void)n_in; (void)out_size;
}

// round 10
// speedup vs baseline: 6.0214x; 1.0065x over previous
#include <cuda_runtime.h>
#include <cuda_fp16.h>
#include <cstdint>
#include <math.h>

#define BATCH   16384
#define IN_DIM  1024
#define NE      6
#define ND      20
#define H1D     256
#define H2D     128
#define EOUT    10
#define GHID    64
#define THID    64

// ---- scratch (device globals; no allocations allowed) ----
__device__ __half g_xh[BATCH * IN_DIM];        // fp16, k-permuted per 32-chunk (32 MB)
__device__ __half g_w1h[NE * H1D * IN_DIM];    // fp16, [e][n][k-perm]          (3 MB)
__device__ __half g_w2h[NE * H2D * H1D];       // fp16, [e][n][k-perm]          (384 KB)
__device__ __half g_gw1h[ND * GHID * IN_DIM];  // fp16, [d][n][k-perm]          (2.6 MB)
__device__ __half g_h1h[BATCH * NE * H1D];     // fp16, [m][e*256 + perm]       (50 MB)
__device__ float  g_eo[BATCH * NE * EOUT];     // fp32 [b][e][o]                (3.9 MB)
__device__ int    g_cnt[ND];
__device__ int    g_idx[ND * BATCH];

// ================= helpers =================
__device__ __forceinline__ uint32_t h2_as_u32(__half2 h) {
    return *(uint32_t*)&h;
}
// k-permutation within a 32-chunk: thread-in-group t (= (k&7)>>1) gets its 8
// needed halves {2t,2t+1, +8, +16, +24} contiguous -> one 16B LDG per K=32.
__device__ __host__ __forceinline__ int perm16(int k) {
    return ((k & 7) >> 1) * 8 + (k >> 3) * 2 + (k & 1);
}
__device__ __forceinline__ void mma16(float* c,
                                      uint32_t a0, uint32_t a1, uint32_t a2, uint32_t a3,
                                      uint32_t b0, uint32_t b1) {
    asm volatile(
        "mma.sync.aligned.m16n8k16.row.col.f32.f16.f16.f32 "
        "{%0,%1,%2,%3}, {%4,%5,%6,%7}, {%8,%9}, {%0,%1,%2,%3};"
        : "+f"(c[0]), "+f"(c[1]), "+f"(c[2]), "+f"(c[3])
        : "r"(a0), "r"(a1), "r"(a2), "r"(a3), "r"(b0), "r"(b1));
}

// ================= bucketing =================
__global__ void zero_cnt_kernel() {
    if (threadIdx.x < ND) g_cnt[threadIdx.x] = 0;
}
__global__ void bucket_kernel(const int* __restrict__ dom) {
    int b = blockIdx.x * blockDim.x + threadIdx.x;
    if (b < BATCH) {
        int d = dom[b];
        int p = atomicAdd(&g_cnt[d], 1);
        g_idx[d * BATCH + p] = b;
    }
}

// ================= prep: X -> fp16, k-permuted (8 elems/thread) =================
__global__ void x_prep_kernel(const float* __restrict__ X) {
    int idx = blockIdx.x * 256 + threadIdx.x;        // 2M threads
    int m = idx >> 7;
    int rest = idx & 127;
    int c = rest >> 2, t = rest & 3;                 // chunk, group
    const float* src = X + (size_t)m * IN_DIM + c * 32 + 2 * t;
    float2 v0 = *(const float2*)(src + 0);
    float2 v1 = *(const float2*)(src + 8);
    float2 v2 = *(const float2*)(src + 16);
    float2 v3 = *(const float2*)(src + 24);
    uint4 o;
    o.x = h2_as_u32(__floats2half2_rn(v0.x, v0.y));
    o.y = h2_as_u32(__floats2half2_rn(v1.x, v1.y));
    o.z = h2_as_u32(__floats2half2_rn(v2.x, v2.y));
    o.w = h2_as_u32(__floats2half2_rn(v3.x, v3.y));
    *(uint4*)(g_xh + (size_t)m * IN_DIM + c * 32 + t * 8) = o;
}

// ================= prep: W [e][K][N] -> [e][n][k-perm] fp16 =================
__global__ void w_prep_kernel(const float* __restrict__ W, __half* __restrict__ WT,
                              int K, int N) {
    __shared__ float tile[32][33];
    int e = blockIdx.z;
    int k0 = blockIdx.x * 32, n0 = blockIdx.y * 32;
    const float* Wp = W + (size_t)e * K * N;
    __half* Tp = WT + (size_t)e * N * K;
    int tx = threadIdx.x, ty = threadIdx.y;   // 32 x 8
#pragma unroll
    for (int j = 0; j < 32; j += 8)
        tile[ty + j][tx] = Wp[(size_t)(k0 + ty + j) * N + n0 + tx];
    __syncthreads();
#pragma unroll
    for (int j = 0; j < 32; j += 8)
        Tp[(size_t)(n0 + ty + j) * K + k0 + perm16(tx)] = __float2half_rn(tile[tx][ty + j]);
}

// ================= expert L1: direct-LDG fp16 mma GEMM (no SMEM) =================
// grid (128, 2, 6). Fragments loaded straight from permuted global layout.
__global__ __launch_bounds__(256, 2)
void expert_l1_mma(const float* __restrict__ bias)
{
    const int tid = threadIdx.x, lane = tid & 31, wid = tid >> 5;
    const int gid = lane >> 2, tig = lane & 3;
    const int warpM = wid & 3, warpN = wid >> 2;
    const int m0 = blockIdx.x * 128;
    const int n0 = blockIdx.y * 128;
    const int e  = blockIdx.z;

    // per-thread fragment base pointers (16B segments, warp-coalesced)
    const __half* Ap = g_xh + (size_t)(m0 + warpM * 32 + gid) * IN_DIM + tig * 8;
    const __half* Bp = g_w1h + (size_t)(e * H1D + n0 + warpN * 64 + gid) * IN_DIM + tig * 8;

    float acc[2][8][4];
#pragma unroll
    for (int mt = 0; mt < 2; mt++)
#pragma unroll
        for (int nt = 0; nt < 8; nt++)
#pragma unroll
            for (int q = 0; q < 4; q++) acc[mt][nt][q] = 0.f;

#pragma unroll 2
    for (int c = 0; c < IN_DIM / 32; c++) {
        const __half* Ac = Ap + c * 32;
        const __half* Bc = Bp + c * 32;
        uint4 Ar[2][2];
#pragma unroll
        for (int mt = 0; mt < 2; mt++)
#pragma unroll
            for (int rr = 0; rr < 2; rr++)
                Ar[mt][rr] = *(const uint4*)(Ac + (mt * 16 + rr * 8) * IN_DIM);
#pragma unroll
        for (int nt = 0; nt < 8; nt++) {
            uint4 Br = *(const uint4*)(Bc + nt * 8 * IN_DIM);
#pragma unroll
            for (int mt = 0; mt < 2; mt++) {
                mma16(acc[mt][nt], Ar[mt][0].x, Ar[mt][1].x, Ar[mt][0].y, Ar[mt][1].y, Br.x, Br.y);
                mma16(acc[mt][nt], Ar[mt][0].z, Ar[mt][1].z, Ar[mt][0].w, Ar[mt][1].w, Br.z, Br.w);
            }
        }
    }

    // epilogue: bias + relu -> fp16 permuted; one STG.128 per (mt,rr,cc)
#pragma unroll
    for (int mt = 0; mt < 2; mt++)
#pragma unroll
        for (int rr = 0; rr < 2; rr++) {
            int row = m0 + warpM * 32 + mt * 16 + rr * 8 + gid;
#pragma unroll
            for (int cc = 0; cc < 2; cc++) {
                uint32_t v[4];
#pragma unroll
                for (int q = 0; q < 4; q++) {
                    int nt = cc * 4 + q;
                    int nn = n0 + warpN * 64 + nt * 8 + tig * 2;
                    float b0 = bias[e * H1D + nn];
                    float b1 = bias[e * H1D + nn + 1];
                    v[q] = h2_as_u32(__floats2half2_rn(
                        fmaxf(acc[mt][nt][rr * 2 + 0] + b0, 0.f),
                        fmaxf(acc[mt][nt][rr * 2 + 1] + b1, 0.f)));
                }
                char* dst = (char*)g_h1h + (size_t)row * (NE * H1D * 2) + e * (H1D * 2)
                          + (size_t)(n0 / 32 + warpN * 2 + cc) * 64 + tig * 16;
                *(uint4*)dst = make_uint4(v[0], v[1], v[2], v[3]);
            }
        }
}

// ================= expert L2 (+fused L3): direct-LDG fp16 mma GEMM =================
#define CS_PITCH 132
__global__ __launch_bounds__(256, 2)
void expert_l2_mma(const float* __restrict__ b2, const float* __restrict__ W3,
                   const float* __restrict__ b3)
{
    extern __shared__ uint32_t sm[];
    float* Cs   = (float*)sm;                          // [128][132] epilogue buffer
    float* sW3  = (float*)((char*)sm + 128 * CS_PITCH * 4);
    float* sEb3 = sW3 + H2D * EOUT;

    const int tid = threadIdx.x, lane = tid & 31, wid = tid >> 5;
    const int gid = lane >> 2, tig = lane & 3;
    const int warpM = wid & 3, warpN = wid >> 2;
    const int m0 = blockIdx.x * 128;
    const int e  = blockIdx.z;

    for (int i = tid; i < H2D * EOUT; i += 256) sW3[i] = W3[e * H2D * EOUT + i];
    if (tid < EOUT) sEb3[tid] = b3[e * EOUT + tid];

    const __half* Ap = g_h1h + (size_t)(m0 + warpM * 32 + gid) * (NE * H1D) + e * H1D + tig * 8;
    const __half* Bp = g_w2h + (size_t)(e * H2D + warpN * 64 + gid) * H1D + tig * 8;

    float acc[2][8][4];
#pragma unroll
    for (int mt = 0; mt < 2; mt++)
#pragma unroll
        for (int nt = 0; nt < 8; nt++)
#pragma unroll
            for (int q = 0; q < 4; q++) acc[mt][nt][q] = 0.f;

#pragma unroll
    for (int c = 0; c < H1D / 32; c++) {
        const __half* Ac = Ap + c * 32;
        const __half* Bc = Bp + c * 32;
        uint4 Ar[2][2];
#pragma unroll
        for (int mt = 0; mt < 2; mt++)
#pragma unroll
            for (int rr = 0; rr < 2; rr++)
                Ar[mt][rr] = *(const uint4*)(Ac + (mt * 16 + rr * 8) * (NE * H1D));
#pragma unroll
        for (int nt = 0; nt < 8; nt++) {
            uint4 Br = *(const uint4*)(Bc + nt * 8 * H1D);
#pragma unroll
            for (int mt = 0; mt < 2; mt++) {
                mma16(acc[mt][nt], Ar[mt][0].x, Ar[mt][1].x, Ar[mt][0].y, Ar[mt][1].y, Br.x, Br.y);
                mma16(acc[mt][nt], Ar[mt][0].z, Ar[mt][1].z, Ar[mt][0].w, Ar[mt][1].w, Br.z, Br.w);
            }
        }
    }

    // epilogue: relu(h2 + b2) into smem, then fused L3 head
    __syncthreads();
#pragma unroll
    for (int mt = 0; mt < 2; mt++) {
        int r = warpM * 32 + mt * 16 + gid;
#pragma unroll
        for (int nt = 0; nt < 8; nt++) {
            int cc = warpN * 64 + nt * 8 + tig * 2;
            float bb0 = b2[e * H2D + cc];
            float bb1 = b2[e * H2D + cc + 1];
            Cs[r * CS_PITCH + cc]           = fmaxf(acc[mt][nt][0] + bb0, 0.f);
            Cs[r * CS_PITCH + cc + 1]       = fmaxf(acc[mt][nt][1] + bb1, 0.f);
            Cs[(r + 8) * CS_PITCH + cc]     = fmaxf(acc[mt][nt][2] + bb0, 0.f);
            Cs[(r + 8) * CS_PITCH + cc + 1] = fmaxf(acc[mt][nt][3] + bb1, 0.f);
        }
    }
    __syncthreads();

    for (int rr = 0; rr < 16; rr++) {
        int row = wid * 16 + rr;
        float p[EOUT];
#pragma unroll
        for (int o = 0; o < EOUT; o++) p[o] = 0.f;
#pragma unroll
        for (int q = 0; q < 4; q++) {
            float hv = Cs[row * CS_PITCH + q * 32 + lane];
            const float* w = &sW3[(q * 32 + lane) * EOUT];
#pragma unroll
            for (int o = 0; o < EOUT; o++) p[o] += hv * w[o];
        }
#pragma unroll
        for (int off = 16; off > 0; off >>= 1)
#pragma unroll
            for (int o = 0; o < EOUT; o++)
                p[o] += __shfl_down_sync(0xffffffffu, p[o], off);
        if (lane == 0) {
            float* dst = &g_eo[(size_t)(m0 + row) * (NE * EOUT) + e * EOUT];
#pragma unroll
            for (int o = 0; o < EOUT; o++) dst[o] = p[o] + sEb3[o];
        }
    }
}

// ================= gate (direct-LDG fp16 mma) + softmax + mmoe + avg + tower ===
__global__ __launch_bounds__(256, 2)
void gate_tower_mma(const float* __restrict__ Gb1,
                    const float* __restrict__ Gw2, const float* __restrict__ Gb2,
                    const float* __restrict__ Tw1, const float* __restrict__ Tb1,
                    const float* __restrict__ Tw2, const float* __restrict__ Tb2,
                    float* __restrict__ out)
{
    extern __shared__ uint32_t sm[];
    float* gh = (float*)sm;                            // [64][68]
    float* P     = (float*)((char*)sm + 64 * 68 * 4);
    float* sGw2  = P;                 // 384
    float* sGb2  = P + 384;           // 8
    float* sTw1  = P + 392;           // 640
    float* sTb1  = P + 1032;          // 64
    float* sTw2  = P + 1096;          // 64
    float* sGb1  = P + 1160;          // 64
    float* sTb2  = P + 1224;          // 1 (+pad)
    int*   sIdx  = (int*)(P + 1228);  // 64

    const int d    = blockIdx.x;
    const int base = blockIdx.y * 64;
    const int cnt  = g_cnt[d];
    if (base >= cnt) return;
    const int nrows = min(64, cnt - base);

    const int tid = threadIdx.x, lane = tid & 31, wid = tid >> 5;
    const int gid = lane >> 2, tig = lane & 3;
    const int warpM = wid & 3, warpN = wid >> 2;   // 4 x 2

    if (tid < 64)
        sIdx[tid] = (tid < nrows) ? g_idx[d * BATCH + base + tid]
                                  : g_idx[d * BATCH + base];
    for (int i = tid; i < GHID * NE; i += 256) sGw2[i] = Gw2[d * GHID * NE + i];
    if (tid < NE) sGb2[tid] = Gb2[d * NE + tid];
    for (int i = tid; i < EOUT * THID; i += 256) sTw1[i] = Tw1[d * EOUT * THID + i];
    if (tid < THID) {
        sTb1[tid] = Tb1[d * THID + tid];
        sTw2[tid] = Tw2[d * THID + tid];
        sGb1[tid] = Gb1[d * GHID + tid];
    }
    if (tid == 0) sTb2[0] = Tb2[d];
    __syncthreads();

    // per-thread gathered A pointers + B pointer
    const __half* Ap0 = g_xh + (size_t)sIdx[warpM * 16 + gid] * IN_DIM + tig * 8;
    const __half* Ap1 = g_xh + (size_t)sIdx[warpM * 16 + 8 + gid] * IN_DIM + tig * 8;
    const __half* Bp  = g_gw1h + (size_t)(d * GHID + warpN * 32 + gid) * IN_DIM + tig * 8;

    float acc[4][4];
#pragma unroll
    for (int nt = 0; nt < 4; nt++)
#pragma unroll
        for (int q = 0; q < 4; q++) acc[nt][q] = 0.f;

#pragma unroll 2
    for (int c = 0; c < IN_DIM / 32; c++) {
        uint4 A0 = *(const uint4*)(Ap0 + c * 32);
        uint4 A1 = *(const uint4*)(Ap1 + c * 32);
#pragma unroll
        for (int nt = 0; nt < 4; nt++) {
            uint4 Br = *(const uint4*)(Bp + nt * 8 * IN_DIM + c * 32);
            mma16(acc[nt], A0.x, A1.x, A0.y, A1.y, Br.x, Br.y);
            mma16(acc[nt], A0.z, A1.z, A0.w, A1.w, Br.z, Br.w);
        }
    }

    // gh = relu(acc + Gb1)
#pragma unroll
    for (int nt = 0; nt < 4; nt++) {
        int cc = warpN * 32 + nt * 8 + tig * 2;
        int r0 = warpM * 16 + gid;
        float b0 = sGb1[cc], b1 = sGb1[cc + 1];
        gh[r0 * 68 + cc]           = fmaxf(acc[nt][0] + b0, 0.f);
        gh[r0 * 68 + cc + 1]       = fmaxf(acc[nt][1] + b1, 0.f);
        gh[(r0 + 8) * 68 + cc]     = fmaxf(acc[nt][2] + b0, 0.f);
        gh[(r0 + 8) * 68 + cc + 1] = fmaxf(acc[nt][3] + b1, 0.f);
    }
    __syncthreads();

    // per-sample epilogue: logits -> softmax -> mmoe -> tower
    if (tid < nrows) {
        const int m = tid;
        const int b = sIdx[m];

        float l[NE];
#pragma unroll
        for (int e = 0; e < NE; e++) l[e] = sGb2[e];
        for (int k = 0; k < GHID; k++) {
            float hv = gh[m * 68 + k];
#pragma unroll
            for (int e = 0; e < NE; e++) l[e] += hv * sGw2[k * NE + e];
        }
        float mx = l[0];
#pragma unroll
        for (int e = 1; e < NE; e++) mx = fmaxf(mx, l[e]);
        float ssum = 0.f;
#pragma unroll
        for (int e = 0; e < NE; e++) { l[e] = expf(l[e] - mx); ssum += l[e]; }
        float inv = 1.f / ssum;

        float mmoe[EOUT], avg[EOUT];
#pragma unroll
        for (int o = 0; o < EOUT; o++) { mmoe[o] = 0.f; avg[o] = 0.f; }
        const float* eorow = g_eo + (size_t)b * (NE * EOUT);
#pragma unroll
        for (int e = 0; e < NE; e++) {
            float gte = l[e] * inv;
#pragma unroll
            for (int o = 0; o < EOUT; o++) {
                float v = eorow[e * EOUT + o];
                mmoe[o] += gte * v;
                avg[o]  += v;
            }
        }
#pragma unroll
        for (int o = 0; o < EOUT; o++) {
            out[BATCH + (size_t)b * EOUT + o]      = avg[o] * (1.f / 6.f);
            out[11 * BATCH + (size_t)b * EOUT + o] = mmoe[o];
        }
        float tacc = sTb2[0];
        for (int h = 0; h < THID; h++) {
            float th = sTb1[h];
#pragma unroll
            for (int o = 0; o < EOUT; o++) th += mmoe[o] * sTw1[o * THID + h];
            th = fmaxf(th, 0.f);
            tacc += th * sTw2[h];
        }
        out[b] = 1.f / (1.f + expf(-tacc));
    }
}

// ------------------------------------------------------------------
extern "C" void kernel_launch(void* const* d_in, const int* in_sizes, int n_in,
                              void* d_out, int out_size)
{
    const float* x    = (const float*)d_in[0];
    const int*   dom  = (const int*)d_in[1];
    const float* Ew1  = (const float*)d_in[2];
    const float* Eb1  = (const float*)d_in[3];
    const float* Ew2  = (const float*)d_in[4];
    const float* Eb2  = (const float*)d_in[5];
    const float* Ew3  = (const float*)d_in[6];
    const float* Eb3  = (const float*)d_in[7];
    const float* Gw1  = (const float*)d_in[8];
    const float* Gb1  = (const float*)d_in[9];
    const float* Gw2  = (const float*)d_in[10];
    const float* Gb2  = (const float*)d_in[11];
    const float* Tw1  = (const float*)d_in[12];
    const float* Tb1  = (const float*)d_in[13];
    const float* Tw2  = (const float*)d_in[14];
    const float* Tb2  = (const float*)d_in[15];
    float* out = (float*)d_out;

    __half* w1h = nullptr; __half* w2h = nullptr; __half* gw1h = nullptr;
    cudaGetSymbolAddress((void**)&w1h,  g_w1h);
    cudaGetSymbolAddress((void**)&w2h,  g_w2h);
    cudaGetSymbolAddress((void**)&gw1h, g_gw1h);

    const int SMEM2 = 128 * CS_PITCH * 4 + (H2D * EOUT + 16) * 4;   // 72768
    const int SMEMG = 64 * 68 * 4 + 1292 * 4 + 256;                 // ~23 KB
    cudaFuncSetAttribute(expert_l2_mma, cudaFuncAttributeMaxDynamicSharedMemorySize, SMEM2);
    cudaFuncSetAttribute(gate_tower_mma, cudaFuncAttributeMaxDynamicSharedMemorySize, SMEMG);

    // launch order chosen so ncu (-s 5 -c 1) captures expert_l1_mma
    zero_cnt_kernel<<<1, 32>>>();                                           // 0
    bucket_kernel<<<(BATCH + 255) / 256, 256>>>(dom);                       // 1
    x_prep_kernel<<<(BATCH * IN_DIM / 8) / 256, 256>>>(x);                  // 2
    w_prep_kernel<<<dim3(IN_DIM / 32, H1D / 32, NE), dim3(32, 8)>>>(Ew1, w1h, IN_DIM, H1D);  // 3
    w_prep_kernel<<<dim3(H1D / 32, H2D / 32, NE), dim3(32, 8)>>>(Ew2, w2h, H1D, H2D);        // 4
    expert_l1_mma<<<dim3(BATCH / 128, 2, NE), 256>>>(Eb1);                  // 5 <- profiled
    w_prep_kernel<<<dim3(IN_DIM / 32, GHID / 32, ND), dim3(32, 8)>>>(Gw1, gw1h, IN_DIM, GHID); // 6
    expert_l2_mma<<<dim3(BATCH / 128, 1, NE), 256, SMEM2>>>(Eb2, Ew3, Eb3); // 7
    gate_tower_mma<<<dim3(ND, (BATCH + 63) / 64), 256, SMEMG>>>(            // 8
        Gb1, Gw2, Gb2, Tw1, Tb1, Tw2, Tb2, out);

    (void)in_sizes; (void)n_in; (void)out_size;
}